// round 1
// baseline (speedup 1.0000x reference)
#include <cuda_runtime.h>
#include <cstdint>

#define HEADS   8
#define DH      32
#define MLEN    1024
#define NPROB   64          // B * HEADS * RATE = 4*8*2
#define BATCH   4
#define SEQ     2046
#define NPAD    2048
#define DMODEL  256

#define BM      64
#define BN      64
#define KPAD    36          // row pitch (floats) for K/Q/V tiles, 16B aligned
#define PPITCH  68          // row pitch for score tile, 16B aligned
#define NT      256

// scratch: qkv reorganized per problem [prob][i][d], prob = ((b*8+h)*2+r)
__device__ float g_qkv[NPROB * MLEN * DH];

// ---------------------------------------------------------------------------
// Kernel 1: qkv = pad(x) @ W + b, written directly into per-problem layout.
// Grid (64, 4): block = 32 consecutive padded rows of one batch, 256 threads
// (one per output column). Rows n >= 2046 use x-row = 0 -> qkv = bias.
// ---------------------------------------------------------------------------
__global__ __launch_bounds__(256) void qkv_proj(
    const float* __restrict__ x, const float* __restrict__ W,
    const float* __restrict__ bias) {
  __shared__ __align__(16) float xsT[DMODEL * 36];  // transposed x tile [d][row]
  const int b  = blockIdx.y;
  const int n0 = blockIdx.x * 32;
  const int c  = threadIdx.x;

  // load 32 rows x 256 cols, transposed into smem (coalesced over d = c)
  #pragma unroll
  for (int rr = 0; rr < 32; ++rr) {
    int n = n0 + rr;
    float v = 0.0f;
    if (n < SEQ) v = x[((size_t)b * SEQ + n) * DMODEL + c];
    xsT[c * 36 + rr] = v;
  }
  __syncthreads();

  float acc[32];
  #pragma unroll
  for (int rr = 0; rr < 32; ++rr) acc[rr] = 0.0f;

  #pragma unroll 4
  for (int d = 0; d < DMODEL; ++d) {
    float w = W[d * DMODEL + c];                         // coalesced, L2-resident
    const float4* xr = reinterpret_cast<const float4*>(xsT + d * 36);
    #pragma unroll
    for (int q = 0; q < 8; ++q) {
      float4 xv = xr[q];                                 // broadcast LDS.128
      acc[4*q+0] = fmaf(xv.x, w, acc[4*q+0]);
      acc[4*q+1] = fmaf(xv.y, w, acc[4*q+1]);
      acc[4*q+2] = fmaf(xv.z, w, acc[4*q+2]);
      acc[4*q+3] = fmaf(xv.w, w, acc[4*q+3]);
    }
  }

  const float bv = bias[c];
  const int h = c >> 5, dd = c & 31;
  #pragma unroll
  for (int rr = 0; rr < 32; ++rr) {
    int n = n0 + rr;
    int i = n >> 1, rbit = n & 1;
    g_qkv[((((size_t)b * HEADS + h) * 2 + rbit) * MLEN + i) * DH + dd] =
        acc[rr] + bv;
  }
}

// ---------------------------------------------------------------------------
// Kernel 2: flash-style attention, Q/K roles swapped.
// One block = one (problem, 64-row tile). Row t's query is k_t; columns are
// q_i with values v_i (Q=K=V = the same per-problem [1024,32] matrix).
// Online softmax over 16 column tiles + 3-entry local epilogue.
// Thread map A (S compute):  ty=tid>>4 rows 4ty..4ty+3, tx=tid&15 cols 4tx..4tx+3
// Thread map B (O update):   rows 4ty..4ty+3, d-cols 2tx, 2tx+1
// ---------------------------------------------------------------------------
__global__ __launch_bounds__(256) void attn(float* __restrict__ out) {
  const int blk  = blockIdx.x;
  const int prob = blk >> 4;          // 16 row tiles per problem
  const int tile = blk & 15;
  const int t0   = tile * BM;
  const int rbit = prob & 1;
  const int h    = (prob >> 1) & 7;
  const int b    = prob >> 4;
  const float* __restrict__ base = g_qkv + (size_t)prob * (MLEN * DH);
  const int tid = threadIdx.x;
  const int ty = tid >> 4, tx = tid & 15;
  const float scale = 0.17677669529663687f;  // 1/sqrt(32)

  __shared__ __align__(16) float Kq[BM * KPAD];   // scaled k_t rows (queries)
  __shared__ __align__(16) float Qk[BN * KPAD];   // q_i / v_i tile (same data)
  __shared__ __align__(16) float Ps[BM * PPITCH]; // score / prob tile
  __shared__ float rowM[BM], rowL[BM], rowC[BM];
  __shared__ float pe0[BM], pe1[BM], pe2[BM];

  for (int idx = tid; idx < BM * DH; idx += NT) {
    int rr = idx >> 5, dd = idx & 31;
    Kq[rr * KPAD + dd] = base[(size_t)(t0 + rr) * DH + dd] * scale;
  }
  if (tid < BM) { rowM[tid] = -3.0e38f; rowL[tid] = 0.0f; }

  float O00=0.f,O01=0.f,O10=0.f,O11=0.f,O20=0.f,O21=0.f,O30=0.f,O31=0.f;
  __syncthreads();

  for (int it = 0; it < MLEN / BN; ++it) {
    const int i0 = it * BN;
    // ---- load column tile (q_i == v_i) ----
    for (int idx = tid; idx < BN * DH; idx += NT) {
      int rr = idx >> 5, dd = idx & 31;
      Qk[rr * KPAD + dd] = base[(size_t)(i0 + rr) * DH + dd];
    }
    __syncthreads();

    // ---- S = Kq(scaled) . Qk^T, 4x4 register tile ----
    float s[4][4];
    #pragma unroll
    for (int a = 0; a < 4; ++a)
      #pragma unroll
      for (int bb = 0; bb < 4; ++bb) s[a][bb] = 0.0f;

    const float* ka = Kq + (4 * ty) * KPAD;
    const float* qb = Qk + (4 * tx) * KPAD;
    #pragma unroll
    for (int k4 = 0; k4 < 8; ++k4) {
      float4 Af[4], Bf[4];
      #pragma unroll
      for (int u = 0; u < 4; ++u) Af[u] = *(const float4*)(ka + u * KPAD + 4 * k4);
      #pragma unroll
      for (int u = 0; u < 4; ++u) Bf[u] = *(const float4*)(qb + u * KPAD + 4 * k4);
      #pragma unroll
      for (int a = 0; a < 4; ++a)
        #pragma unroll
        for (int bb = 0; bb < 4; ++bb) {
          s[a][bb] = fmaf(Af[a].x, Bf[bb].x, s[a][bb]);
          s[a][bb] = fmaf(Af[a].y, Bf[bb].y, s[a][bb]);
          s[a][bb] = fmaf(Af[a].z, Bf[bb].z, s[a][bb]);
          s[a][bb] = fmaf(Af[a].w, Bf[bb].w, s[a][bb]);
        }
    }
    #pragma unroll
    for (int a = 0; a < 4; ++a) {
      float4 v4 = make_float4(s[a][0], s[a][1], s[a][2], s[a][3]);
      *(float4*)(Ps + (size_t)(4 * ty + a) * PPITCH + 4 * tx) = v4;
    }
    __syncthreads();

    // ---- online softmax per row (threads 0..63, one row each) ----
    if (tid < BM) {
      float* pr = Ps + (size_t)tid * PPITCH;
      float mo = rowM[tid];
      float mx = mo;
      #pragma unroll
      for (int j4 = 0; j4 < 16; ++j4) {
        float4 v = *(const float4*)(pr + 4 * j4);
        mx = fmaxf(mx, fmaxf(fmaxf(v.x, v.y), fmaxf(v.z, v.w)));
      }
      float corr = __expf(mo - mx);
      float l = rowL[tid] * corr;
      #pragma unroll
      for (int j4 = 0; j4 < 16; ++j4) {
        float4 v = *(const float4*)(pr + 4 * j4);
        float4 p;
        p.x = __expf(v.x - mx); p.y = __expf(v.y - mx);
        p.z = __expf(v.z - mx); p.w = __expf(v.w - mx);
        l += p.x + p.y + p.z + p.w;
        *(float4*)(pr + 4 * j4) = p;
      }
      rowM[tid] = mx; rowL[tid] = l; rowC[tid] = corr;
    }
    __syncthreads();

    // ---- O = O*corr + P @ V ----
    {
      float c0 = rowC[4*ty+0], c1 = rowC[4*ty+1], c2 = rowC[4*ty+2], c3 = rowC[4*ty+3];
      O00 *= c0; O01 *= c0; O10 *= c1; O11 *= c1;
      O20 *= c2; O21 *= c2; O30 *= c3; O31 *= c3;
      const float* p0r = Ps + (size_t)(4*ty+0) * PPITCH;
      const float* p1r = Ps + (size_t)(4*ty+1) * PPITCH;
      const float* p2r = Ps + (size_t)(4*ty+2) * PPITCH;
      const float* p3r = Ps + (size_t)(4*ty+3) * PPITCH;
      #pragma unroll 8
      for (int j = 0; j < BN; ++j) {
        float2 v = *(const float2*)(Qk + (size_t)j * KPAD + 2 * tx);
        float p0 = p0r[j], p1 = p1r[j], p2 = p2r[j], p3 = p3r[j];
        O00 = fmaf(p0, v.x, O00); O01 = fmaf(p0, v.y, O01);
        O10 = fmaf(p1, v.x, O10); O11 = fmaf(p1, v.y, O11);
        O20 = fmaf(p2, v.x, O20); O21 = fmaf(p2, v.y, O21);
        O30 = fmaf(p3, v.x, O30); O31 = fmaf(p3, v.y, O31);
      }
    }
    __syncthreads();
  }

  // ---- epilogue: 3 local logits q_t . {k_{t-1}, k_t, k_{t+1}} ----
  // Out-of-range patches are ZERO vectors in the reference -> logit exactly 0
  // (still included in softmax), value contribution 0.
  if (tid < BM) {
    const int row = tid;
    const int t = t0 + row;
    const float* qt = base + (size_t)t * DH;
    float d0 = 0.f, d1 = 0.f, d2 = 0.f;
    #pragma unroll
    for (int kk = 0; kk < DH; ++kk) { float q = qt[kk]; d1 = fmaf(q, q, d1); }
    if (t > 0) {
      const float* km = base + (size_t)(t - 1) * DH;
      #pragma unroll
      for (int kk = 0; kk < DH; ++kk) d0 = fmaf(qt[kk], km[kk], d0);
    }
    if (t < MLEN - 1) {
      const float* kp = base + (size_t)(t + 1) * DH;
      #pragma unroll
      for (int kk = 0; kk < DH; ++kk) d2 = fmaf(qt[kk], kp[kk], d2);
    }
    float e0 = (t > 0)        ? d0 * scale : 0.0f;
    float e1 = d1 * scale;
    float e2 = (t < MLEN - 1) ? d2 * scale : 0.0f;
    float mo = rowM[row];
    float mx = fmaxf(fmaxf(mo, e0), fmaxf(e1, e2));
    float corr = __expf(mo - mx);
    float l = rowL[row] * corr;
    float p0 = __expf(e0 - mx), p1 = __expf(e1 - mx), p2 = __expf(e2 - mx);
    l += p0 + p1 + p2;                 // zero-vector logits still count in denom
    pe0[row] = (t > 0)        ? p0 : 0.0f;
    pe1[row] = p1;
    pe2[row] = (t < MLEN - 1) ? p2 : 0.0f;
    rowC[row] = corr;
    rowL[row] = l;
  }
  __syncthreads();

  // ---- final: add local values, normalize, write (drop padded rows) ----
  #pragma unroll
  for (int rr = 0; rr < 4; ++rr) {
    const int row = 4 * ty + rr;
    const int t = t0 + row;
    const float corr = rowC[row];
    const float linv = 1.0f / rowL[row];
    const int n = 2 * t + rbit;
    float oc[2] = { (rr==0?O00:rr==1?O10:rr==2?O20:O30),
                    (rr==0?O01:rr==1?O11:rr==2?O21:O31) };
    #pragma unroll
    for (int cc = 0; cc < 2; ++cc) {
      const int c = 2 * tx + cc;
      float acc = oc[cc] * corr;
      acc = fmaf(pe1[row], base[(size_t)t * DH + c], acc);
      if (t > 0)        acc = fmaf(pe0[row], base[(size_t)(t - 1) * DH + c], acc);
      if (t < MLEN - 1) acc = fmaf(pe2[row], base[(size_t)(t + 1) * DH + c], acc);
      if (n < SEQ)
        out[((size_t)b * SEQ + n) * DMODEL + h * DH + c] = acc * linv;
    }
  }
}

// ---------------------------------------------------------------------------
extern "C" void kernel_launch(void* const* d_in, const int* in_sizes, int n_in,
                              void* d_out, int out_size) {
  const float* x    = (const float*)d_in[0];
  const float* W    = (const float*)d_in[1];
  const float* bias = (const float*)d_in[2];
  float* out = (float*)d_out;

  qkv_proj<<<dim3(NPAD / 32, BATCH), 256>>>(x, W, bias);
  attn<<<NPROB * (MLEN / BM), 256>>>(out);
}

// round 2
// speedup vs baseline: 3.2411x; 3.2411x over previous
#include <cuda_runtime.h>
#include <cstdint>

#define HEADS   8
#define DH      32
#define MLEN    1024
#define NPROB   64          // B * HEADS * RATE
#define BATCH   4
#define SEQ     2046
#define NPAD    2048
#define DMODEL  256

#define BM      64
#define BN      64

__device__ float g_qkv[NPROB * MLEN * DH];

// ---------------------------------------------------------------------------
// Kernel 1: qkv = pad(x) @ W + b  -> per-problem [1024,32] layout (unchanged)
// ---------------------------------------------------------------------------
__global__ __launch_bounds__(256) void qkv_proj(
    const float* __restrict__ x, const float* __restrict__ W,
    const float* __restrict__ bias) {
  __shared__ __align__(16) float xsT[DMODEL * 36];
  const int b  = blockIdx.y;
  const int n0 = blockIdx.x * 32;
  const int c  = threadIdx.x;

  #pragma unroll
  for (int rr = 0; rr < 32; ++rr) {
    int n = n0 + rr;
    float v = 0.0f;
    if (n < SEQ) v = x[((size_t)b * SEQ + n) * DMODEL + c];
    xsT[c * 36 + rr] = v;
  }
  __syncthreads();

  float acc[32];
  #pragma unroll
  for (int rr = 0; rr < 32; ++rr) acc[rr] = 0.0f;

  #pragma unroll 4
  for (int d = 0; d < DMODEL; ++d) {
    float w = W[d * DMODEL + c];
    const float4* xr = reinterpret_cast<const float4*>(xsT + d * 36);
    #pragma unroll
    for (int q = 0; q < 8; ++q) {
      float4 xv = xr[q];
      acc[4*q+0] = fmaf(xv.x, w, acc[4*q+0]);
      acc[4*q+1] = fmaf(xv.y, w, acc[4*q+1]);
      acc[4*q+2] = fmaf(xv.z, w, acc[4*q+2]);
      acc[4*q+3] = fmaf(xv.w, w, acc[4*q+3]);
    }
  }

  const float bv = bias[c];
  const int h = c >> 5, dd = c & 31;
  #pragma unroll
  for (int rr = 0; rr < 32; ++rr) {
    int n = n0 + rr;
    int i = n >> 1, rbit = n & 1;
    g_qkv[((((size_t)b * HEADS + h) * 2 + rbit) * MLEN + i) * DH + dd] =
        acc[rr] + bv;
  }
}

// ---------------------------------------------------------------------------
// tf32 helpers
// ---------------------------------------------------------------------------
__device__ __forceinline__ uint32_t f2tf32(float f) {
  uint32_t u;
  asm("cvt.rna.tf32.f32 %0, %1;" : "=r"(u) : "f"(f));
  return u;
}

__device__ __forceinline__ void mma_tf32(float c[4],
    uint32_t a0, uint32_t a1, uint32_t a2, uint32_t a3,
    uint32_t b0, uint32_t b1) {
  asm volatile(
    "mma.sync.aligned.m16n8k8.row.col.f32.tf32.tf32.f32 "
    "{%0,%1,%2,%3},{%4,%5,%6,%7},{%8,%9},{%0,%1,%2,%3};"
    : "+f"(c[0]), "+f"(c[1]), "+f"(c[2]), "+f"(c[3])
    : "r"(a0), "r"(a1), "r"(a2), "r"(a3), "r"(b0), "r"(b1));
}

// ---------------------------------------------------------------------------
// Kernel 2: tensor-core flash attention, no-max softmax.
// Block = one (problem, 64-row tile), 128 threads (4 warps, 2x2 warp grid).
// S-stage: warp computes 32x32 of S = (scale*K) @ Q^T over k=32 (tf32 mma).
// exp in registers (no max), row-sums accumulate in registers across tiles,
// P -> tf32 -> smem. PV-stage: O(64x32) accumulates in mma fragments across
// all 16 column tiles. Final: add 3-entry local logits (fp32), normalize.
// ---------------------------------------------------------------------------
__global__ __launch_bounds__(128) void attn(float* __restrict__ out) {
  const int blk  = blockIdx.x;
  const int prob = blk >> 4;
  const int tile = blk & 15;
  const int t0   = tile * BM;
  const int rbit = prob & 1;
  const int h    = (prob >> 1) & 7;
  const int b    = prob >> 4;
  const float* __restrict__ base = g_qkv + (size_t)prob * (MLEN * DH);
  const int tid  = threadIdx.x;
  const int warp = tid >> 5, lane = tid & 31;
  const int wm = warp >> 1, wn = warp & 1;
  const int qrow = lane >> 2, qk = lane & 3;
  const uint32_t swzA = (uint32_t)(qrow << 2);   // 4*(row&7) when row%8 == qrow
  const float scale = 0.17677669529663687f;

  __shared__ __align__(16) uint32_t Ks[BM * 32];  // scale*K, tf32, swizzled
  __shared__ __align__(16) uint32_t Qs[BN * 32];  // Q / V tile, tf32, swizzled
  __shared__ __align__(16) uint32_t Ps[BM * 64];  // P, tf32, swizzled
  __shared__ float rowLp[2 * BM];
  __shared__ float pe0[BM], pe1[BM], pe2[BM], linv[BM];

  // load K tile (pre-scaled)
  #pragma unroll
  for (int e = 0; e < 16; ++e) {
    int idx = tid + 128 * e;
    int r = idx >> 5, c = idx & 31;
    float v = base[(size_t)(t0 + r) * DH + c] * scale;
    Ks[r * 32 + (c ^ ((r & 7) << 2))] = f2tf32(v);
  }

  float O[2][2][4];
  #pragma unroll
  for (int i = 0; i < 2; ++i)
    #pragma unroll
    for (int j = 0; j < 2; ++j)
      #pragma unroll
      for (int k = 0; k < 4; ++k) O[i][j][k] = 0.0f;
  float rsum[4] = {0.f, 0.f, 0.f, 0.f};

  for (int it = 0; it < MLEN / BN; ++it) {
    const float* src = base + (size_t)it * BN * DH;
    #pragma unroll
    for (int e = 0; e < 16; ++e) {
      int idx = tid + 128 * e;
      int r = idx >> 5, c = idx & 31;
      Qs[r * 32 + (c ^ ((r & 7) << 2))] = f2tf32(src[r * 32 + c]);
    }
    __syncthreads();

    // ---- S = Ks @ Qs^T (per warp 32x32) ----
    float acc[2][4][4];
    #pragma unroll
    for (int mt = 0; mt < 2; ++mt)
      #pragma unroll
      for (int nt = 0; nt < 4; ++nt)
        #pragma unroll
        for (int k = 0; k < 4; ++k) acc[mt][nt][k] = 0.0f;

    #pragma unroll
    for (int kc = 0; kc < 4; ++kc) {
      const int k0 = kc * 8 + qk, k1 = k0 + 4;
      uint32_t a[2][4];
      #pragma unroll
      for (int mt = 0; mt < 2; ++mt) {
        int rb = wm * 32 + mt * 16 + qrow;
        a[mt][0] = Ks[rb * 32 + (k0 ^ swzA)];
        a[mt][1] = Ks[(rb + 8) * 32 + (k0 ^ swzA)];
        a[mt][2] = Ks[rb * 32 + (k1 ^ swzA)];
        a[mt][3] = Ks[(rb + 8) * 32 + (k1 ^ swzA)];
      }
      uint32_t bf[4][2];
      #pragma unroll
      for (int nt = 0; nt < 4; ++nt) {
        int nr = wn * 32 + nt * 8 + qrow;
        bf[nt][0] = Qs[nr * 32 + (k0 ^ swzA)];
        bf[nt][1] = Qs[nr * 32 + (k1 ^ swzA)];
      }
      #pragma unroll
      for (int mt = 0; mt < 2; ++mt)
        #pragma unroll
        for (int nt = 0; nt < 4; ++nt)
          mma_tf32(acc[mt][nt], a[mt][0], a[mt][1], a[mt][2], a[mt][3],
                   bf[nt][0], bf[nt][1]);
    }

    // ---- exp (no max), row-sum accumulate, P -> smem ----
    #pragma unroll
    for (int mt = 0; mt < 2; ++mt) {
      int rb = wm * 32 + mt * 16 + qrow;
      #pragma unroll
      for (int nt = 0; nt < 4; ++nt) {
        float p0 = __expf(acc[mt][nt][0]);
        float p1 = __expf(acc[mt][nt][1]);
        float p2 = __expf(acc[mt][nt][2]);
        float p3 = __expf(acc[mt][nt][3]);
        rsum[mt * 2 + 0] += p0 + p1;
        rsum[mt * 2 + 1] += p2 + p3;
        int col = wn * 32 + nt * 8 + 2 * qk;
        uint2 lo = make_uint2(f2tf32(p0), f2tf32(p1));
        uint2 hi = make_uint2(f2tf32(p2), f2tf32(p3));
        *reinterpret_cast<uint2*>(&Ps[rb * 64 + (col ^ swzA)]) = lo;
        *reinterpret_cast<uint2*>(&Ps[(rb + 8) * 64 + (col ^ swzA)]) = hi;
      }
    }
    __syncthreads();

    // ---- O += P @ V  (V == Qs) ----
    #pragma unroll
    for (int kc = 0; kc < 8; ++kc) {
      const int j0 = kc * 8 + qk, j1 = j0 + 4;
      uint32_t a[2][4];
      #pragma unroll
      for (int mt = 0; mt < 2; ++mt) {
        int rb = wm * 32 + mt * 16 + qrow;
        a[mt][0] = Ps[rb * 64 + (j0 ^ swzA)];
        a[mt][1] = Ps[(rb + 8) * 64 + (j0 ^ swzA)];
        a[mt][2] = Ps[rb * 64 + (j1 ^ swzA)];
        a[mt][3] = Ps[(rb + 8) * 64 + (j1 ^ swzA)];
      }
      uint32_t bf[2][2];
      #pragma unroll
      for (int nt = 0; nt < 2; ++nt) {
        int d = wn * 16 + nt * 8 + qrow;
        bf[nt][0] = Qs[j0 * 32 + (d ^ ((j0 & 7) << 2))];
        bf[nt][1] = Qs[j1 * 32 + (d ^ ((j1 & 7) << 2))];
      }
      #pragma unroll
      for (int mt = 0; mt < 2; ++mt)
        #pragma unroll
        for (int nt = 0; nt < 2; ++nt)
          mma_tf32(O[mt][nt], a[mt][0], a[mt][1], a[mt][2], a[mt][3],
                   bf[nt][0], bf[nt][1]);
    }
    __syncthreads();
  }

  // ---- row-sum reduce across the 4 lanes sharing a row ----
  #pragma unroll
  for (int s = 0; s < 4; ++s) {
    rsum[s] += __shfl_xor_sync(0xffffffffu, rsum[s], 1);
    rsum[s] += __shfl_xor_sync(0xffffffffu, rsum[s], 2);
  }
  if (qk == 0) {
    #pragma unroll
    for (int s = 0; s < 4; ++s) {
      int r = wm * 32 + (s >> 1) * 16 + (s & 1) * 8 + qrow;
      rowLp[wn * BM + r] = rsum[s];
    }
  }
  __syncthreads();

  // ---- local epilogue: 3 logits in full fp32, finish denominators ----
  if (tid < BM) {
    const int row = tid;
    const int t = t0 + row;
    const float* qt = base + (size_t)t * DH;
    float d0 = 0.f, d1 = 0.f, d2 = 0.f;
    #pragma unroll
    for (int kk = 0; kk < DH; ++kk) { float q = qt[kk]; d1 = fmaf(q, q, d1); }
    if (t > 0) {
      const float* km = base + (size_t)(t - 1) * DH;
      #pragma unroll
      for (int kk = 0; kk < DH; ++kk) d0 = fmaf(qt[kk], km[kk], d0);
    }
    if (t < MLEN - 1) {
      const float* kp = base + (size_t)(t + 1) * DH;
      #pragma unroll
      for (int kk = 0; kk < DH; ++kk) d2 = fmaf(qt[kk], kp[kk], d2);
    }
    float e0 = (t > 0)        ? d0 * scale : 0.0f;   // zero patch -> logit 0
    float e1 = d1 * scale;
    float e2 = (t < MLEN - 1) ? d2 * scale : 0.0f;
    float p0 = __expf(e0), p1 = __expf(e1), p2 = __expf(e2);
    float L = rowLp[row] + rowLp[BM + row] + p0 + p1 + p2;
    pe0[row] = (t > 0)        ? p0 : 0.0f;
    pe1[row] = p1;
    pe2[row] = (t < MLEN - 1) ? p2 : 0.0f;
    linv[row] = 1.0f / L;
  }
  __syncthreads();

  // ---- final write: add local values (fp32), normalize ----
  #pragma unroll
  for (int mt = 0; mt < 2; ++mt) {
    #pragma unroll
    for (int half = 0; half < 2; ++half) {
      const int r = wm * 32 + mt * 16 + half * 8 + qrow;
      const int t = t0 + r;
      const int n = 2 * t + rbit;
      if (n >= SEQ) continue;
      const float inv = linv[r];
      const float w0 = pe0[r], w1 = pe1[r], w2 = pe2[r];
      #pragma unroll
      for (int nt = 0; nt < 2; ++nt) {
        const int cb = wn * 16 + nt * 8 + 2 * qk;
        float cx = O[mt][nt][half * 2 + 0];
        float cy = O[mt][nt][half * 2 + 1];
        float2 vc = *reinterpret_cast<const float2*>(&base[(size_t)t * DH + cb]);
        float ax = fmaf(w1, vc.x, cx);
        float ay = fmaf(w1, vc.y, cy);
        if (t > 0) {
          float2 vm = *reinterpret_cast<const float2*>(&base[(size_t)(t - 1) * DH + cb]);
          ax = fmaf(w0, vm.x, ax);
          ay = fmaf(w0, vm.y, ay);
        }
        if (t < MLEN - 1) {
          float2 vp = *reinterpret_cast<const float2*>(&base[(size_t)(t + 1) * DH + cb]);
          ax = fmaf(w2, vp.x, ax);
          ay = fmaf(w2, vp.y, ay);
        }
        float2 o = make_float2(ax * inv, ay * inv);
        *reinterpret_cast<float2*>(
            &out[((size_t)b * SEQ + n) * DMODEL + h * DH + cb]) = o;
      }
    }
  }
}

// ---------------------------------------------------------------------------
extern "C" void kernel_launch(void* const* d_in, const int* in_sizes, int n_in,
                              void* d_out, int out_size) {
  const float* x    = (const float*)d_in[0];
  const float* W    = (const float*)d_in[1];
  const float* bias = (const float*)d_in[2];
  float* out = (float*)d_out;

  qkv_proj<<<dim3(NPAD / 32, BATCH), 256>>>(x, W, bias);
  attn<<<NPROB * (MLEN / BM), 128>>>(out);
}

// round 3
// speedup vs baseline: 3.5218x; 1.0866x over previous
#include <cuda_runtime.h>
#include <cstdint>

#define HEADS   8
#define DH      32
#define MLEN    1024
#define NPROB   64          // B * HEADS * RATE
#define BATCH   4
#define SEQ     2046
#define NPAD    2048
#define DMODEL  256

#define BM      64
#define BN      64
#define OPITCH  34          // Obuf pitch (even, conflict-free across qrow)

__device__ float g_qkv[NPROB * MLEN * DH];

// ---------------------------------------------------------------------------
// Kernel 1: qkv = pad(x) @ W + b  -> per-problem [1024,32] layout (unchanged)
// ---------------------------------------------------------------------------
__global__ __launch_bounds__(256) void qkv_proj(
    const float* __restrict__ x, const float* __restrict__ W,
    const float* __restrict__ bias) {
  __shared__ __align__(16) float xsT[DMODEL * 36];
  const int b  = blockIdx.y;
  const int n0 = blockIdx.x * 32;
  const int c  = threadIdx.x;

  #pragma unroll
  for (int rr = 0; rr < 32; ++rr) {
    int n = n0 + rr;
    float v = 0.0f;
    if (n < SEQ) v = x[((size_t)b * SEQ + n) * DMODEL + c];
    xsT[c * 36 + rr] = v;
  }
  __syncthreads();

  float acc[32];
  #pragma unroll
  for (int rr = 0; rr < 32; ++rr) acc[rr] = 0.0f;

  #pragma unroll 4
  for (int d = 0; d < DMODEL; ++d) {
    float w = W[d * DMODEL + c];
    const float4* xr = reinterpret_cast<const float4*>(xsT + d * 36);
    #pragma unroll
    for (int q = 0; q < 8; ++q) {
      float4 xv = xr[q];
      acc[4*q+0] = fmaf(xv.x, w, acc[4*q+0]);
      acc[4*q+1] = fmaf(xv.y, w, acc[4*q+1]);
      acc[4*q+2] = fmaf(xv.z, w, acc[4*q+2]);
      acc[4*q+3] = fmaf(xv.w, w, acc[4*q+3]);
    }
  }

  const float bv = bias[c];
  const int h = c >> 5, dd = c & 31;
  #pragma unroll
  for (int rr = 0; rr < 32; ++rr) {
    int n = n0 + rr;
    int i = n >> 1, rbit = n & 1;
    g_qkv[((((size_t)b * HEADS + h) * 2 + rbit) * MLEN + i) * DH + dd] =
        acc[rr] + bv;
  }
}

// ---------------------------------------------------------------------------
// tf32 helpers
// ---------------------------------------------------------------------------
__device__ __forceinline__ uint32_t f2tf32(float f) {
  uint32_t u;
  asm("cvt.rna.tf32.f32 %0, %1;" : "=r"(u) : "f"(f));
  return u;
}

__device__ __forceinline__ void mma_tf32(float c[4],
    uint32_t a0, uint32_t a1, uint32_t a2, uint32_t a3,
    uint32_t b0, uint32_t b1) {
  asm volatile(
    "mma.sync.aligned.m16n8k8.row.col.f32.tf32.tf32.f32 "
    "{%0,%1,%2,%3},{%4,%5,%6,%7},{%8,%9},{%0,%1,%2,%3};"
    : "+f"(c[0]), "+f"(c[1]), "+f"(c[2]), "+f"(c[3])
    : "r"(a0), "r"(a1), "r"(a2), "r"(a3), "r"(b0), "r"(b1));
}

// ---------------------------------------------------------------------------
// Kernel 2: tensor-core flash attention, no-max softmax, register-resident P.
// 128 threads = 4 warps, 2x2 (wm: 32-row half, wn: 32-column half).
// Per tile: S = Ks@Q^T (K A-frags hoisted), exp in regs, P redistributed to
// mma A-fragments by warp shuffles (no smem), partial O += P@V over this
// warp's 32 columns. Column-half partials summed once at the end via smem.
// ---------------------------------------------------------------------------
__global__ __launch_bounds__(128) void attn(float* __restrict__ out) {
  const int blk  = blockIdx.x;
  const int prob = blk >> 4;
  const int tile = blk & 15;
  const int t0   = tile * BM;
  const int rbit = prob & 1;
  const int h    = (prob >> 1) & 7;
  const int b    = prob >> 4;
  const float* __restrict__ base = g_qkv + (size_t)prob * (MLEN * DH);
  const int tid  = threadIdx.x;
  const int warp = tid >> 5, lane = tid & 31;
  const int wm = warp >> 1, wn = warp & 1;
  const int qrow = lane >> 2, qk = lane & 3;
  const uint32_t swzA = (uint32_t)(qrow << 2);
  const float scale = 0.17677669529663687f;   // 1/sqrt(32)

  __shared__ __align__(16) uint32_t Ks[BM * 32];
  __shared__ __align__(16) uint32_t Qs[2][BN * 32];
  __shared__ float Obuf[BM * OPITCH];
  __shared__ float rowLp[2 * BM];
  __shared__ float pe0[BM], pe1[BM], pe2[BM], linv[BM];

  // ---- fill Ks (scaled, tf32, swizzled), float4 path ----
  #pragma unroll
  for (int e = 0; e < 4; ++e) {
    int f = tid + 128 * e;
    int r = f >> 3, c = (f & 7) << 2;
    float4 v = *reinterpret_cast<const float4*>(base + (size_t)(t0 + r) * DH + c);
    uint4 u;
    u.x = f2tf32(v.x * scale); u.y = f2tf32(v.y * scale);
    u.z = f2tf32(v.z * scale); u.w = f2tf32(v.w * scale);
    *reinterpret_cast<uint4*>(&Ks[r * 32 + (c ^ ((r & 7) << 2))]) = u;
  }
  // ---- fill Qs[0] (tile 0) ----
  #pragma unroll
  for (int e = 0; e < 4; ++e) {
    int f = tid + 128 * e;
    int r = f >> 3, c = (f & 7) << 2;
    float4 v = *reinterpret_cast<const float4*>(base + (size_t)r * DH + c);
    uint4 u;
    u.x = f2tf32(v.x); u.y = f2tf32(v.y); u.z = f2tf32(v.z); u.w = f2tf32(v.w);
    *reinterpret_cast<uint4*>(&Qs[0][r * 32 + (c ^ ((r & 7) << 2))]) = u;
  }
  __syncthreads();

  // ---- hoist K A-fragments (loop-invariant) ----
  uint32_t A[2][4][4];
  #pragma unroll
  for (int mt = 0; mt < 2; ++mt) {
    const int rb = wm * 32 + mt * 16 + qrow;
    #pragma unroll
    for (int kc = 0; kc < 4; ++kc) {
      const int k0 = kc * 8 + qk;
      A[mt][kc][0] = Ks[rb * 32 + (k0 ^ swzA)];
      A[mt][kc][1] = Ks[(rb + 8) * 32 + (k0 ^ swzA)];
      A[mt][kc][2] = Ks[rb * 32 + ((k0 + 4) ^ swzA)];
      A[mt][kc][3] = Ks[(rb + 8) * 32 + ((k0 + 4) ^ swzA)];
    }
  }

  float O[2][4][4];
  #pragma unroll
  for (int i = 0; i < 2; ++i)
    #pragma unroll
    for (int j = 0; j < 4; ++j)
      #pragma unroll
      for (int k = 0; k < 4; ++k) O[i][j][k] = 0.0f;
  float rsum[4] = {0.f, 0.f, 0.f, 0.f};

  const int src0 = (lane & 28) | (qk >> 1);
  const int src1 = src0 + 2;
  const bool odd = (qk & 1) != 0;

  for (int it = 0; it < MLEN / BN; ++it) {
    const uint32_t* __restrict__ Qc = Qs[it & 1];

    // prefetch next tile into registers (hidden behind compute)
    float4 pf[4];
    if (it < MLEN / BN - 1) {
      const float* nsrc = base + (size_t)(it + 1) * BN * DH;
      #pragma unroll
      for (int e = 0; e < 4; ++e) {
        int f = tid + 128 * e;
        pf[e] = *reinterpret_cast<const float4*>(nsrc + (f >> 3) * 32 + ((f & 7) << 2));
      }
    }

    #pragma unroll
    for (int g = 0; g < 4; ++g) {
      // ---- S for column group g (n = 8 cols of this warp's 32) ----
      float acc[2][4] = {{0.f,0.f,0.f,0.f},{0.f,0.f,0.f,0.f}};
      const int nc = wn * 32 + g * 8 + qrow;
      #pragma unroll
      for (int kc = 0; kc < 4; ++kc) {
        const int k0 = kc * 8 + qk;
        uint32_t b0 = Qc[nc * 32 + (k0 ^ swzA)];
        uint32_t b1 = Qc[nc * 32 + ((k0 + 4) ^ swzA)];
        mma_tf32(acc[0], A[0][kc][0], A[0][kc][1], A[0][kc][2], A[0][kc][3], b0, b1);
        mma_tf32(acc[1], A[1][kc][0], A[1][kc][1], A[1][kc][2], A[1][kc][3], b0, b1);
      }

      // ---- exp (no max), row-sum, tf32 pack ----
      uint32_t pu[2][4];
      #pragma unroll
      for (int mt = 0; mt < 2; ++mt) {
        #pragma unroll
        for (int e = 0; e < 4; ++e) {
          float p = __expf(acc[mt][e]);
          rsum[mt * 2 + (e >> 1)] += p;
          pu[mt][e] = f2tf32(p);
        }
      }

      // ---- shuffle P accumulator fragments -> mma A fragments ----
      uint32_t aP[2][4];
      #pragma unroll
      for (int mt = 0; mt < 2; ++mt) {
        uint32_t x0 = __shfl_sync(0xffffffffu, pu[mt][0], src0);
        uint32_t x1 = __shfl_sync(0xffffffffu, pu[mt][1], src0);
        uint32_t x2 = __shfl_sync(0xffffffffu, pu[mt][2], src0);
        uint32_t x3 = __shfl_sync(0xffffffffu, pu[mt][3], src0);
        uint32_t y0 = __shfl_sync(0xffffffffu, pu[mt][0], src1);
        uint32_t y1 = __shfl_sync(0xffffffffu, pu[mt][1], src1);
        uint32_t y2 = __shfl_sync(0xffffffffu, pu[mt][2], src1);
        uint32_t y3 = __shfl_sync(0xffffffffu, pu[mt][3], src1);
        aP[mt][0] = odd ? x1 : x0;
        aP[mt][1] = odd ? x3 : x2;
        aP[mt][2] = odd ? y1 : y0;
        aP[mt][3] = odd ? y3 : y2;
      }

      // ---- partial O += P(:, g-group) @ V(g-group, :) ----
      const int jr0 = wn * 32 + g * 8 + qk;
      const int jr1 = jr0 + 4;
      const uint32_t swz0 = (uint32_t)((jr0 & 7) << 2);
      const uint32_t swz1 = (uint32_t)((jr1 & 7) << 2);
      #pragma unroll
      for (int ntd = 0; ntd < 4; ++ntd) {
        const int d = ntd * 8 + qrow;
        uint32_t vb0 = Qc[jr0 * 32 + (d ^ swz0)];
        uint32_t vb1 = Qc[jr1 * 32 + (d ^ swz1)];
        mma_tf32(O[0][ntd], aP[0][0], aP[0][1], aP[0][2], aP[0][3], vb0, vb1);
        mma_tf32(O[1][ntd], aP[1][0], aP[1][1], aP[1][2], aP[1][3], vb0, vb1);
      }
    }

    // ---- store prefetched tile into the other buffer ----
    if (it < MLEN / BN - 1) {
      uint32_t* Qn = Qs[(it + 1) & 1];
      #pragma unroll
      for (int e = 0; e < 4; ++e) {
        int f = tid + 128 * e;
        int r = f >> 3, c = (f & 7) << 2;
        uint4 u;
        u.x = f2tf32(pf[e].x); u.y = f2tf32(pf[e].y);
        u.z = f2tf32(pf[e].z); u.w = f2tf32(pf[e].w);
        *reinterpret_cast<uint4*>(&Qn[r * 32 + (c ^ ((r & 7) << 2))]) = u;
      }
    }
    __syncthreads();
  }

  // ---- reduce row sums across the 4 lanes of each row ----
  #pragma unroll
  for (int s = 0; s < 4; ++s) {
    rsum[s] += __shfl_xor_sync(0xffffffffu, rsum[s], 1);
    rsum[s] += __shfl_xor_sync(0xffffffffu, rsum[s], 2);
  }
  if (qk == 0) {
    #pragma unroll
    for (int s = 0; s < 4; ++s) {
      int r = wm * 32 + (s >> 1) * 16 + (s & 1) * 8 + qrow;
      rowLp[wn * BM + r] = rsum[s];
    }
  }

  // ---- column-half wn==1 parks its partial O in smem ----
  if (wn == 1) {
    #pragma unroll
    for (int mt = 0; mt < 2; ++mt) {
      const int r = wm * 32 + mt * 16 + qrow;
      #pragma unroll
      for (int ntd = 0; ntd < 4; ++ntd) {
        const int cb = ntd * 8 + 2 * qk;
        *reinterpret_cast<float2*>(&Obuf[r * OPITCH + cb]) =
            make_float2(O[mt][ntd][0], O[mt][ntd][1]);
        *reinterpret_cast<float2*>(&Obuf[(r + 8) * OPITCH + cb]) =
            make_float2(O[mt][ntd][2], O[mt][ntd][3]);
      }
    }
  }
  __syncthreads();

  // ---- local epilogue: 3 logits in full fp32, finish denominators ----
  if (tid < BM) {
    const int row = tid;
    const int t = t0 + row;
    const float* qt = base + (size_t)t * DH;
    float d0 = 0.f, d1 = 0.f, d2 = 0.f;
    #pragma unroll
    for (int kk = 0; kk < DH; ++kk) { float q = qt[kk]; d1 = fmaf(q, q, d1); }
    if (t > 0) {
      const float* km = base + (size_t)(t - 1) * DH;
      #pragma unroll
      for (int kk = 0; kk < DH; ++kk) d0 = fmaf(qt[kk], km[kk], d0);
    }
    if (t < MLEN - 1) {
      const float* kp = base + (size_t)(t + 1) * DH;
      #pragma unroll
      for (int kk = 0; kk < DH; ++kk) d2 = fmaf(qt[kk], kp[kk], d2);
    }
    float e0 = (t > 0)        ? d0 * scale : 0.0f;   // zero patch -> logit 0
    float e1 = d1 * scale;
    float e2 = (t < MLEN - 1) ? d2 * scale : 0.0f;
    float p0 = __expf(e0), p1 = __expf(e1), p2 = __expf(e2);
    float L = rowLp[row] + rowLp[BM + row] + p0 + p1 + p2;
    pe0[row] = (t > 0)        ? p0 : 0.0f;
    pe1[row] = p1;
    pe2[row] = (t < MLEN - 1) ? p2 : 0.0f;
    linv[row] = 1.0f / L;
  }
  __syncthreads();

  // ---- final: wn==0 warps combine halves, add local values, write ----
  if (wn == 0) {
    #pragma unroll
    for (int mt = 0; mt < 2; ++mt) {
      #pragma unroll
      for (int half = 0; half < 2; ++half) {
        const int r = wm * 32 + mt * 16 + half * 8 + qrow;
        const int t = t0 + r;
        const int n = 2 * t + rbit;
        if (n >= SEQ) continue;
        const float inv = linv[r];
        const float w0 = pe0[r], w1 = pe1[r], w2 = pe2[r];
        #pragma unroll
        for (int ntd = 0; ntd < 4; ++ntd) {
          const int cb = ntd * 8 + 2 * qk;
          float2 oo = *reinterpret_cast<const float2*>(&Obuf[r * OPITCH + cb]);
          float ax = O[mt][ntd][half * 2 + 0] + oo.x;
          float ay = O[mt][ntd][half * 2 + 1] + oo.y;
          float2 vc = *reinterpret_cast<const float2*>(&base[(size_t)t * DH + cb]);
          ax = fmaf(w1, vc.x, ax);
          ay = fmaf(w1, vc.y, ay);
          if (t > 0) {
            float2 vm = *reinterpret_cast<const float2*>(&base[(size_t)(t - 1) * DH + cb]);
            ax = fmaf(w0, vm.x, ax);
            ay = fmaf(w0, vm.y, ay);
          }
          if (t < MLEN - 1) {
            float2 vp = *reinterpret_cast<const float2*>(&base[(size_t)(t + 1) * DH + cb]);
            ax = fmaf(w2, vp.x, ax);
            ay = fmaf(w2, vp.y, ay);
          }
          *reinterpret_cast<float2*>(
              &out[((size_t)b * SEQ + n) * DMODEL + h * DH + cb]) =
              make_float2(ax * inv, ay * inv);
        }
      }
    }
  }
}

// ---------------------------------------------------------------------------
extern "C" void kernel_launch(void* const* d_in, const int* in_sizes, int n_in,
                              void* d_out, int out_size) {
  const float* x    = (const float*)d_in[0];
  const float* W    = (const float*)d_in[1];
  const float* bias = (const float*)d_in[2];
  float* out = (float*)d_out;

  qkv_proj<<<dim3(NPAD / 32, BATCH), 256>>>(x, W, bias);
  attn<<<NPROB * (MLEN / BM), 128>>>(out);
}

// round 4
// speedup vs baseline: 3.9092x; 1.1100x over previous
#include <cuda_runtime.h>
#include <cstdint>

#define HEADS   8
#define DH      32
#define MLEN    1024
#define NPROB   64          // B * HEADS * RATE
#define BATCH   4
#define SEQ     2046
#define NPAD    2048
#define DMODEL  256

#define BM      64
#define BN      64
#define OPITCH  34          // Obuf pitch (even, conflict-free across qrow)

__device__ float g_qkv[NPROB * MLEN * DH];

// ---------------------------------------------------------------------------
// Kernel 1: qkv = pad(x) @ W + b  -> per-problem [1024,32] layout
// ---------------------------------------------------------------------------
__global__ __launch_bounds__(256) void qkv_proj(
    const float* __restrict__ x, const float* __restrict__ W,
    const float* __restrict__ bias) {
  __shared__ __align__(16) float xsT[DMODEL * 36];
  const int b  = blockIdx.y;
  const int n0 = blockIdx.x * 32;
  const int c  = threadIdx.x;

  #pragma unroll
  for (int rr = 0; rr < 32; ++rr) {
    int n = n0 + rr;
    float v = 0.0f;
    if (n < SEQ) v = x[((size_t)b * SEQ + n) * DMODEL + c];
    xsT[c * 36 + rr] = v;
  }
  __syncthreads();

  float acc[32];
  #pragma unroll
  for (int rr = 0; rr < 32; ++rr) acc[rr] = 0.0f;

  #pragma unroll 4
  for (int d = 0; d < DMODEL; ++d) {
    float w = W[d * DMODEL + c];
    const float4* xr = reinterpret_cast<const float4*>(xsT + d * 36);
    #pragma unroll
    for (int q = 0; q < 8; ++q) {
      float4 xv = xr[q];
      acc[4*q+0] = fmaf(xv.x, w, acc[4*q+0]);
      acc[4*q+1] = fmaf(xv.y, w, acc[4*q+1]);
      acc[4*q+2] = fmaf(xv.z, w, acc[4*q+2]);
      acc[4*q+3] = fmaf(xv.w, w, acc[4*q+3]);
    }
  }

  const float bv = bias[c];
  const int h = c >> 5, dd = c & 31;
  #pragma unroll
  for (int rr = 0; rr < 32; ++rr) {
    int n = n0 + rr;
    int i = n >> 1, rbit = n & 1;
    g_qkv[((((size_t)b * HEADS + h) * 2 + rbit) * MLEN + i) * DH + dd] =
        acc[rr] + bv;
  }
}

// ---------------------------------------------------------------------------
// tf32 helpers
// ---------------------------------------------------------------------------
__device__ __forceinline__ uint32_t f2tf32(float f) {
  uint32_t u;
  asm("cvt.rna.tf32.f32 %0, %1;" : "=r"(u) : "f"(f));
  return u;
}

__device__ __forceinline__ void mma_tf32(float c[4],
    uint32_t a0, uint32_t a1, uint32_t a2, uint32_t a3,
    uint32_t b0, uint32_t b1) {
  asm volatile(
    "mma.sync.aligned.m16n8k8.row.col.f32.tf32.tf32.f32 "
    "{%0,%1,%2,%3},{%4,%5,%6,%7},{%8,%9},{%0,%1,%2,%3};"
    : "+f"(c[0]), "+f"(c[1]), "+f"(c[2]), "+f"(c[3])
    : "r"(a0), "r"(a1), "r"(a2), "r"(a3), "r"(b0), "r"(b1));
}

// ---------------------------------------------------------------------------
// Kernel 2: tensor-core flash attention, no-max softmax, ZERO-shuffle P reuse.
// The P@V product is invariant under simultaneous permutation of P's columns
// and V's rows within each k=8 group. Permutation (k-slot s <-> logical col
// 2s|s/4) makes the S accumulator layout exactly the PV A-fragment layout:
//   aP = {c0, c2, c1, c3}    (register renaming, no data movement)
// with V fed in row order j = g*8 + 2*qk, j+1.
// ---------------------------------------------------------------------------
__global__ __launch_bounds__(128) void attn(float* __restrict__ out) {
  const int blk  = blockIdx.x;
  const int prob = blk >> 4;
  const int tile = blk & 15;
  const int t0   = tile * BM;
  const int rbit = prob & 1;
  const int h    = (prob >> 1) & 7;
  const int b    = prob >> 4;
  const float* __restrict__ base = g_qkv + (size_t)prob * (MLEN * DH);
  const int tid  = threadIdx.x;
  const int warp = tid >> 5, lane = tid & 31;
  const int wm = warp >> 1, wn = warp & 1;
  const int qrow = lane >> 2, qk = lane & 3;
  const uint32_t swzA = (uint32_t)(qrow << 2);
  const float scale = 0.17677669529663687f;   // 1/sqrt(32)

  __shared__ __align__(16) uint32_t Ks[BM * 32];
  __shared__ __align__(16) uint32_t Qs[2][BN * 32];
  __shared__ float Obuf[BM * OPITCH];
  __shared__ float rowLp[2 * BM];
  __shared__ float pe0[BM], pe1[BM], pe2[BM], linv[BM];

  // ---- fill Ks (scaled, tf32, swizzled) ----
  #pragma unroll
  for (int e = 0; e < 4; ++e) {
    int f = tid + 128 * e;
    int r = f >> 3, c = (f & 7) << 2;
    float4 v = *reinterpret_cast<const float4*>(base + (size_t)(t0 + r) * DH + c);
    uint4 u;
    u.x = f2tf32(v.x * scale); u.y = f2tf32(v.y * scale);
    u.z = f2tf32(v.z * scale); u.w = f2tf32(v.w * scale);
    *reinterpret_cast<uint4*>(&Ks[r * 32 + (c ^ ((r & 7) << 2))]) = u;
  }
  // ---- fill Qs[0] ----
  #pragma unroll
  for (int e = 0; e < 4; ++e) {
    int f = tid + 128 * e;
    int r = f >> 3, c = (f & 7) << 2;
    float4 v = *reinterpret_cast<const float4*>(base + (size_t)r * DH + c);
    uint4 u;
    u.x = f2tf32(v.x); u.y = f2tf32(v.y); u.z = f2tf32(v.z); u.w = f2tf32(v.w);
    *reinterpret_cast<uint4*>(&Qs[0][r * 32 + (c ^ ((r & 7) << 2))]) = u;
  }
  __syncthreads();

  // ---- hoist K A-fragments (loop-invariant) ----
  uint32_t A[2][4][4];
  #pragma unroll
  for (int mt = 0; mt < 2; ++mt) {
    const int rb = wm * 32 + mt * 16 + qrow;
    #pragma unroll
    for (int kc = 0; kc < 4; ++kc) {
      const int k0 = kc * 8 + qk;
      A[mt][kc][0] = Ks[rb * 32 + (k0 ^ swzA)];
      A[mt][kc][1] = Ks[(rb + 8) * 32 + (k0 ^ swzA)];
      A[mt][kc][2] = Ks[rb * 32 + ((k0 + 4) ^ swzA)];
      A[mt][kc][3] = Ks[(rb + 8) * 32 + ((k0 + 4) ^ swzA)];
    }
  }

  float O[2][4][4];
  #pragma unroll
  for (int i = 0; i < 2; ++i)
    #pragma unroll
    for (int j = 0; j < 4; ++j)
      #pragma unroll
      for (int k = 0; k < 4; ++k) O[i][j][k] = 0.0f;
  float rsum[4] = {0.f, 0.f, 0.f, 0.f};

  for (int it = 0; it < MLEN / BN; ++it) {
    const uint32_t* __restrict__ Qc = Qs[it & 1];

    // prefetch next tile into registers (hidden behind compute)
    float4 pf[4];
    if (it < MLEN / BN - 1) {
      const float* nsrc = base + (size_t)(it + 1) * BN * DH;
      #pragma unroll
      for (int e = 0; e < 4; ++e) {
        int f = tid + 128 * e;
        pf[e] = *reinterpret_cast<const float4*>(nsrc + (f >> 3) * 32 + ((f & 7) << 2));
      }
    }

    #pragma unroll
    for (int g = 0; g < 4; ++g) {
      // ---- S for column group g ----
      float acc[2][4] = {{0.f,0.f,0.f,0.f},{0.f,0.f,0.f,0.f}};
      const int nc = wn * 32 + g * 8 + qrow;
      #pragma unroll
      for (int kc = 0; kc < 4; ++kc) {
        const int k0 = kc * 8 + qk;
        uint32_t b0 = Qc[nc * 32 + (k0 ^ swzA)];
        uint32_t b1 = Qc[nc * 32 + ((k0 + 4) ^ swzA)];
        mma_tf32(acc[0], A[0][kc][0], A[0][kc][1], A[0][kc][2], A[0][kc][3], b0, b1);
        mma_tf32(acc[1], A[1][kc][0], A[1][kc][1], A[1][kc][2], A[1][kc][3], b0, b1);
      }

      // ---- exp (no max), row-sum, tf32 pack; accumulator IS the A-fragment
      //      under the column/row permutation (aP = {c0, c2, c1, c3}) ----
      uint32_t aP[2][4];
      #pragma unroll
      for (int mt = 0; mt < 2; ++mt) {
        float p0 = __expf(acc[mt][0]);
        float p1 = __expf(acc[mt][1]);
        float p2 = __expf(acc[mt][2]);
        float p3 = __expf(acc[mt][3]);
        rsum[mt * 2 + 0] += p0 + p1;
        rsum[mt * 2 + 1] += p2 + p3;
        aP[mt][0] = f2tf32(p0);   // (qrow,   k-slot qk)   = logical col 2qk
        aP[mt][1] = f2tf32(p2);   // (qrow+8, k-slot qk)
        aP[mt][2] = f2tf32(p1);   // (qrow,   k-slot qk+4) = logical col 2qk+1
        aP[mt][3] = f2tf32(p3);   // (qrow+8, k-slot qk+4)
      }

      // ---- partial O += P @ V, V rows fed in permuted order ----
      const int jr0 = wn * 32 + g * 8 + 2 * qk;     // logical col 2qk
      const int jr1 = jr0 + 1;                       // logical col 2qk+1
      const uint32_t swz0 = (uint32_t)((jr0 & 7) << 2);
      const uint32_t swz1 = (uint32_t)((jr1 & 7) << 2);
      #pragma unroll
      for (int ntd = 0; ntd < 4; ++ntd) {
        const int d = ntd * 8 + qrow;
        uint32_t vb0 = Qc[jr0 * 32 + (d ^ swz0)];
        uint32_t vb1 = Qc[jr1 * 32 + (d ^ swz1)];
        mma_tf32(O[0][ntd], aP[0][0], aP[0][1], aP[0][2], aP[0][3], vb0, vb1);
        mma_tf32(O[1][ntd], aP[1][0], aP[1][1], aP[1][2], aP[1][3], vb0, vb1);
      }
    }

    // ---- store prefetched tile into the other buffer ----
    if (it < MLEN / BN - 1) {
      uint32_t* Qn = Qs[(it + 1) & 1];
      #pragma unroll
      for (int e = 0; e < 4; ++e) {
        int f = tid + 128 * e;
        int r = f >> 3, c = (f & 7) << 2;
        uint4 u;
        u.x = f2tf32(pf[e].x); u.y = f2tf32(pf[e].y);
        u.z = f2tf32(pf[e].z); u.w = f2tf32(pf[e].w);
        *reinterpret_cast<uint4*>(&Qn[r * 32 + (c ^ ((r & 7) << 2))]) = u;
      }
    }
    __syncthreads();
  }

  // ---- reduce row sums across the 4 lanes of each row ----
  #pragma unroll
  for (int s = 0; s < 4; ++s) {
    rsum[s] += __shfl_xor_sync(0xffffffffu, rsum[s], 1);
    rsum[s] += __shfl_xor_sync(0xffffffffu, rsum[s], 2);
  }
  if (qk == 0) {
    #pragma unroll
    for (int s = 0; s < 4; ++s) {
      int r = wm * 32 + (s >> 1) * 16 + (s & 1) * 8 + qrow;
      rowLp[wn * BM + r] = rsum[s];
    }
  }

  // ---- column-half wn==1 parks its partial O in smem ----
  if (wn == 1) {
    #pragma unroll
    for (int mt = 0; mt < 2; ++mt) {
      const int r = wm * 32 + mt * 16 + qrow;
      #pragma unroll
      for (int ntd = 0; ntd < 4; ++ntd) {
        const int cb = ntd * 8 + 2 * qk;
        *reinterpret_cast<float2*>(&Obuf[r * OPITCH + cb]) =
            make_float2(O[mt][ntd][0], O[mt][ntd][1]);
        *reinterpret_cast<float2*>(&Obuf[(r + 8) * OPITCH + cb]) =
            make_float2(O[mt][ntd][2], O[mt][ntd][3]);
      }
    }
  }
  __syncthreads();

  // ---- local epilogue: 3 logits in full fp32, finish denominators ----
  if (tid < BM) {
    const int row = tid;
    const int t = t0 + row;
    const float* qt = base + (size_t)t * DH;
    float d0 = 0.f, d1 = 0.f, d2 = 0.f;
    #pragma unroll
    for (int kk = 0; kk < DH; ++kk) { float q = qt[kk]; d1 = fmaf(q, q, d1); }
    if (t > 0) {
      const float* km = base + (size_t)(t - 1) * DH;
      #pragma unroll
      for (int kk = 0; kk < DH; ++kk) d0 = fmaf(qt[kk], km[kk], d0);
    }
    if (t < MLEN - 1) {
      const float* kp = base + (size_t)(t + 1) * DH;
      #pragma unroll
      for (int kk = 0; kk < DH; ++kk) d2 = fmaf(qt[kk], kp[kk], d2);
    }
    float e0 = (t > 0)        ? d0 * scale : 0.0f;   // zero patch -> logit 0
    float e1 = d1 * scale;
    float e2 = (t < MLEN - 1) ? d2 * scale : 0.0f;
    float p0 = __expf(e0), p1 = __expf(e1), p2 = __expf(e2);
    float L = rowLp[row] + rowLp[BM + row] + p0 + p1 + p2;
    pe0[row] = (t > 0)        ? p0 : 0.0f;
    pe1[row] = p1;
    pe2[row] = (t < MLEN - 1) ? p2 : 0.0f;
    linv[row] = 1.0f / L;
  }
  __syncthreads();

  // ---- final: wn==0 warps combine halves, add local values, write ----
  if (wn == 0) {
    #pragma unroll
    for (int mt = 0; mt < 2; ++mt) {
      #pragma unroll
      for (int half = 0; half < 2; ++half) {
        const int r = wm * 32 + mt * 16 + half * 8 + qrow;
        const int t = t0 + r;
        const int n = 2 * t + rbit;
        if (n >= SEQ) continue;
        const float inv = linv[r];
        const float w0 = pe0[r], w1 = pe1[r], w2 = pe2[r];
        #pragma unroll
        for (int ntd = 0; ntd < 4; ++ntd) {
          const int cb = ntd * 8 + 2 * qk;
          float2 oo = *reinterpret_cast<const float2*>(&Obuf[r * OPITCH + cb]);
          float ax = O[mt][ntd][half * 2 + 0] + oo.x;
          float ay = O[mt][ntd][half * 2 + 1] + oo.y;
          float2 vc = *reinterpret_cast<const float2*>(&base[(size_t)t * DH + cb]);
          ax = fmaf(w1, vc.x, ax);
          ay = fmaf(w1, vc.y, ay);
          if (t > 0) {
            float2 vm = *reinterpret_cast<const float2*>(&base[(size_t)(t - 1) * DH + cb]);
            ax = fmaf(w0, vm.x, ax);
            ay = fmaf(w0, vm.y, ay);
          }
          if (t < MLEN - 1) {
            float2 vp = *reinterpret_cast<const float2*>(&base[(size_t)(t + 1) * DH + cb]);
            ax = fmaf(w2, vp.x, ax);
            ay = fmaf(w2, vp.y, ay);
          }
          *reinterpret_cast<float2*>(
              &out[((size_t)b * SEQ + n) * DMODEL + h * DH + cb]) =
              make_float2(ax * inv, ay * inv);
        }
      }
    }
  }
}

// ---------------------------------------------------------------------------
extern "C" void kernel_launch(void* const* d_in, const int* in_sizes, int n_in,
                              void* d_out, int out_size) {
  const float* x    = (const float*)d_in[0];
  const float* W    = (const float*)d_in[1];
  const float* bias = (const float*)d_in[2];
  float* out = (float*)d_out;

  qkv_proj<<<dim3(NPAD / 32, BATCH), 256>>>(x, W, bias);
  attn<<<NPROB * (MLEN / BM), 128>>>(out);
}

// round 6
// speedup vs baseline: 4.8735x; 1.2467x over previous
#include <cuda_runtime.h>
#include <cstdint>

#define HEADS   8
#define DH      32
#define MLEN    1024
#define NPROB   64          // B * HEADS * RATE
#define BATCH   4
#define SEQ     2046
#define NPAD    2048
#define DMODEL  256

#define BM      64
#define BN      64
#define OPITCH  34          // Obuf pitch (even, conflict-free across qrow)

__device__ float g_qkv[NPROB * MLEN * DH];
__device__ uint32_t g_WT[DMODEL * DMODEL];   // W^T in tf32, [c][d]

// ---------------------------------------------------------------------------
// tf32 helpers
// ---------------------------------------------------------------------------
__device__ __forceinline__ uint32_t f2tf32(float f) {
  uint32_t u;
  asm("cvt.rna.tf32.f32 %0, %1;" : "=r"(u) : "f"(f));
  return u;
}

__device__ __forceinline__ void mma_tf32(float c[4],
    uint32_t a0, uint32_t a1, uint32_t a2, uint32_t a3,
    uint32_t b0, uint32_t b1) {
  asm volatile(
    "mma.sync.aligned.m16n8k8.row.col.f32.tf32.tf32.f32 "
    "{%0,%1,%2,%3},{%4,%5,%6,%7},{%8,%9},{%0,%1,%2,%3};"
    : "+f"(c[0]), "+f"(c[1]), "+f"(c[2]), "+f"(c[3])
    : "r"(a0), "r"(a1), "r"(a2), "r"(a3), "r"(b0), "r"(b1));
}

// ---------------------------------------------------------------------------
// Kernel 0: W^T -> tf32 (one-time, tiny). Coalesced read, scattered write.
// ---------------------------------------------------------------------------
__global__ __launch_bounds__(256) void w_transpose(const float* __restrict__ W) {
  int idx = blockIdx.x * 256 + threadIdx.x;   // 65536 elements, grid 256
  int d = idx >> 8, c = idx & 255;
  g_WT[c * DMODEL + d] = f2tf32(W[idx]);
}

// ---------------------------------------------------------------------------
// Kernel 1: qkv = pad(x) @ W + b on tensor cores (tf32), scatter into
// per-problem [1024,32] layout. 256 threads, BM=128 x BN=64, K chunks of 32.
// Warp grid 4(m) x 2(n); each warp computes 32x32 with m16n8k8 fragments.
// M-dimension covers BATCH*NPAD = 8192 rows -> gridDim.x = 64.
// ---------------------------------------------------------------------------
__global__ __launch_bounds__(256) void qkv_gemm(
    const float* __restrict__ x, const float* __restrict__ bias) {
  __shared__ __align__(16) uint32_t Xs[128 * 32];
  __shared__ __align__(16) uint32_t Ws[64 * 32];
  const int m0 = blockIdx.x * 128;
  const int n0 = blockIdx.y * 64;
  const int tid = threadIdx.x;
  const int warp = tid >> 5, lane = tid & 31;
  const int wm = warp >> 1, wn = warp & 1;
  const int qrow = lane >> 2, qk = lane & 3;
  const uint32_t swzA = (uint32_t)(qrow << 2);

  float C[2][4][4];
  #pragma unroll
  for (int i = 0; i < 2; ++i)
    #pragma unroll
    for (int j = 0; j < 4; ++j)
      #pragma unroll
      for (int k = 0; k < 4; ++k) C[i][j][k] = 0.0f;

  for (int kc0 = 0; kc0 < DMODEL; kc0 += 32) {
    // ---- fill Xs[128][32] (tf32, swizzled); padded rows -> 0 ----
    #pragma unroll
    for (int e = 0; e < 4; ++e) {
      int f = tid + 256 * e;          // float4 index 0..1023
      int r = f >> 3, c4 = (f & 7) << 2;
      int m = m0 + r;
      int b = m >> 11, n = m & 2047;
      uint4 u = make_uint4(0u, 0u, 0u, 0u);
      if (n < SEQ) {
        float4 v = *reinterpret_cast<const float4*>(
            x + ((size_t)b * SEQ + n) * DMODEL + kc0 + c4);
        u.x = f2tf32(v.x); u.y = f2tf32(v.y);
        u.z = f2tf32(v.z); u.w = f2tf32(v.w);
      }
      *reinterpret_cast<uint4*>(&Xs[r * 32 + (c4 ^ ((r & 7) << 2))]) = u;
    }
    // ---- fill Ws[64][32] from g_WT (already tf32) ----
    #pragma unroll
    for (int e = 0; e < 2; ++e) {
      int f = tid + 256 * e;          // float4 index 0..511
      int r = f >> 3, c4 = (f & 7) << 2;
      uint4 u = *reinterpret_cast<const uint4*>(
          g_WT + (size_t)(n0 + r) * DMODEL + kc0 + c4);
      *reinterpret_cast<uint4*>(&Ws[r * 32 + (c4 ^ ((r & 7) << 2))]) = u;
    }
    __syncthreads();

    #pragma unroll
    for (int ks = 0; ks < 4; ++ks) {
      const int k0 = ks * 8 + qk;
      uint32_t a[2][4];
      #pragma unroll
      for (int mt = 0; mt < 2; ++mt) {
        const int rb = wm * 32 + mt * 16 + qrow;
        a[mt][0] = Xs[rb * 32 + (k0 ^ swzA)];
        a[mt][1] = Xs[(rb + 8) * 32 + (k0 ^ swzA)];
        a[mt][2] = Xs[rb * 32 + ((k0 + 4) ^ swzA)];
        a[mt][3] = Xs[(rb + 8) * 32 + ((k0 + 4) ^ swzA)];
      }
      uint32_t bf[4][2];
      #pragma unroll
      for (int nt = 0; nt < 4; ++nt) {
        const int nc = wn * 32 + nt * 8 + qrow;
        bf[nt][0] = Ws[nc * 32 + (k0 ^ swzA)];
        bf[nt][1] = Ws[nc * 32 + ((k0 + 4) ^ swzA)];
      }
      #pragma unroll
      for (int mt = 0; mt < 2; ++mt)
        #pragma unroll
        for (int nt = 0; nt < 4; ++nt)
          mma_tf32(C[mt][nt], a[mt][0], a[mt][1], a[mt][2], a[mt][3],
                   bf[nt][0], bf[nt][1]);
    }
    __syncthreads();
  }

  // ---- epilogue: add bias, scatter into g_qkv per-problem layout ----
  #pragma unroll
  for (int nt = 0; nt < 4; ++nt) {
    const int col = n0 + wn * 32 + nt * 8 + 2 * qk;
    const float bx = bias[col], by = bias[col + 1];
    const int h = col >> 5, dd = col & 31;
    #pragma unroll
    for (int mt = 0; mt < 2; ++mt) {
      #pragma unroll
      for (int half = 0; half < 2; ++half) {
        const int r = wm * 32 + mt * 16 + half * 8 + qrow;
        const int m = m0 + r;
        const int b = m >> 11, n = m & 2047;
        const int i = n >> 1, rbit = n & 1;
        float2 val = make_float2(C[mt][nt][half * 2 + 0] + bx,
                                 C[mt][nt][half * 2 + 1] + by);
        *reinterpret_cast<float2*>(
            &g_qkv[((((size_t)b * HEADS + h) * 2 + rbit) * MLEN + i) * DH + dd]) =
            val;
      }
    }
  }
}

// ---------------------------------------------------------------------------
// Kernel 2: tensor-core flash attention, no-max softmax, zero-shuffle P reuse
// (unchanged from R4).
// ---------------------------------------------------------------------------
__global__ __launch_bounds__(128) void attn(float* __restrict__ out) {
  const int blk  = blockIdx.x;
  const int prob = blk >> 4;
  const int tile = blk & 15;
  const int t0   = tile * BM;
  const int rbit = prob & 1;
  const int h    = (prob >> 1) & 7;
  const int b    = prob >> 4;
  const float* __restrict__ base = g_qkv + (size_t)prob * (MLEN * DH);
  const int tid  = threadIdx.x;
  const int warp = tid >> 5, lane = tid & 31;
  const int wm = warp >> 1, wn = warp & 1;
  const int qrow = lane >> 2, qk = lane & 3;
  const uint32_t swzA = (uint32_t)(qrow << 2);
  const float scale = 0.17677669529663687f;   // 1/sqrt(32)

  __shared__ __align__(16) uint32_t Ks[BM * 32];
  __shared__ __align__(16) uint32_t Qs[2][BN * 32];
  __shared__ float Obuf[BM * OPITCH];
  __shared__ float rowLp[2 * BM];
  __shared__ float pe0[BM], pe1[BM], pe2[BM], linv[BM];

  #pragma unroll
  for (int e = 0; e < 4; ++e) {
    int f = tid + 128 * e;
    int r = f >> 3, c = (f & 7) << 2;
    float4 v = *reinterpret_cast<const float4*>(base + (size_t)(t0 + r) * DH + c);
    uint4 u;
    u.x = f2tf32(v.x * scale); u.y = f2tf32(v.y * scale);
    u.z = f2tf32(v.z * scale); u.w = f2tf32(v.w * scale);
    *reinterpret_cast<uint4*>(&Ks[r * 32 + (c ^ ((r & 7) << 2))]) = u;
  }
  #pragma unroll
  for (int e = 0; e < 4; ++e) {
    int f = tid + 128 * e;
    int r = f >> 3, c = (f & 7) << 2;
    float4 v = *reinterpret_cast<const float4*>(base + (size_t)r * DH + c);
    uint4 u;
    u.x = f2tf32(v.x); u.y = f2tf32(v.y); u.z = f2tf32(v.z); u.w = f2tf32(v.w);
    *reinterpret_cast<uint4*>(&Qs[0][r * 32 + (c ^ ((r & 7) << 2))]) = u;
  }
  __syncthreads();

  uint32_t A[2][4][4];
  #pragma unroll
  for (int mt = 0; mt < 2; ++mt) {
    const int rb = wm * 32 + mt * 16 + qrow;
    #pragma unroll
    for (int kc = 0; kc < 4; ++kc) {
      const int k0 = kc * 8 + qk;
      A[mt][kc][0] = Ks[rb * 32 + (k0 ^ swzA)];
      A[mt][kc][1] = Ks[(rb + 8) * 32 + (k0 ^ swzA)];
      A[mt][kc][2] = Ks[rb * 32 + ((k0 + 4) ^ swzA)];
      A[mt][kc][3] = Ks[(rb + 8) * 32 + ((k0 + 4) ^ swzA)];
    }
  }

  float O[2][4][4];
  #pragma unroll
  for (int i = 0; i < 2; ++i)
    #pragma unroll
    for (int j = 0; j < 4; ++j)
      #pragma unroll
      for (int k = 0; k < 4; ++k) O[i][j][k] = 0.0f;
  float rsum[4] = {0.f, 0.f, 0.f, 0.f};

  for (int it = 0; it < MLEN / BN; ++it) {
    const uint32_t* __restrict__ Qc = Qs[it & 1];

    float4 pf[4];
    if (it < MLEN / BN - 1) {
      const float* nsrc = base + (size_t)(it + 1) * BN * DH;
      #pragma unroll
      for (int e = 0; e < 4; ++e) {
        int f = tid + 128 * e;
        pf[e] = *reinterpret_cast<const float4*>(nsrc + (f >> 3) * 32 + ((f & 7) << 2));
      }
    }

    #pragma unroll
    for (int g = 0; g < 4; ++g) {
      float acc[2][4] = {{0.f,0.f,0.f,0.f},{0.f,0.f,0.f,0.f}};
      const int nc = wn * 32 + g * 8 + qrow;
      #pragma unroll
      for (int kc = 0; kc < 4; ++kc) {
        const int k0 = kc * 8 + qk;
        uint32_t b0 = Qc[nc * 32 + (k0 ^ swzA)];
        uint32_t b1 = Qc[nc * 32 + ((k0 + 4) ^ swzA)];
        mma_tf32(acc[0], A[0][kc][0], A[0][kc][1], A[0][kc][2], A[0][kc][3], b0, b1);
        mma_tf32(acc[1], A[1][kc][0], A[1][kc][1], A[1][kc][2], A[1][kc][3], b0, b1);
      }

      uint32_t aP[2][4];
      #pragma unroll
      for (int mt = 0; mt < 2; ++mt) {
        float p0 = __expf(acc[mt][0]);
        float p1 = __expf(acc[mt][1]);
        float p2 = __expf(acc[mt][2]);
        float p3 = __expf(acc[mt][3]);
        rsum[mt * 2 + 0] += p0 + p1;
        rsum[mt * 2 + 1] += p2 + p3;
        aP[mt][0] = f2tf32(p0);
        aP[mt][1] = f2tf32(p2);
        aP[mt][2] = f2tf32(p1);
        aP[mt][3] = f2tf32(p3);
      }

      const int jr0 = wn * 32 + g * 8 + 2 * qk;
      const int jr1 = jr0 + 1;
      const uint32_t swz0 = (uint32_t)((jr0 & 7) << 2);
      const uint32_t swz1 = (uint32_t)((jr1 & 7) << 2);
      #pragma unroll
      for (int ntd = 0; ntd < 4; ++ntd) {
        const int d = ntd * 8 + qrow;
        uint32_t vb0 = Qc[jr0 * 32 + (d ^ swz0)];
        uint32_t vb1 = Qc[jr1 * 32 + (d ^ swz1)];
        mma_tf32(O[0][ntd], aP[0][0], aP[0][1], aP[0][2], aP[0][3], vb0, vb1);
        mma_tf32(O[1][ntd], aP[1][0], aP[1][1], aP[1][2], aP[1][3], vb0, vb1);
      }
    }

    if (it < MLEN / BN - 1) {
      uint32_t* Qn = Qs[(it + 1) & 1];
      #pragma unroll
      for (int e = 0; e < 4; ++e) {
        int f = tid + 128 * e;
        int r = f >> 3, c = (f & 7) << 2;
        uint4 u;
        u.x = f2tf32(pf[e].x); u.y = f2tf32(pf[e].y);
        u.z = f2tf32(pf[e].z); u.w = f2tf32(pf[e].w);
        *reinterpret_cast<uint4*>(&Qn[r * 32 + (c ^ ((r & 7) << 2))]) = u;
      }
    }
    __syncthreads();
  }

  #pragma unroll
  for (int s = 0; s < 4; ++s) {
    rsum[s] += __shfl_xor_sync(0xffffffffu, rsum[s], 1);
    rsum[s] += __shfl_xor_sync(0xffffffffu, rsum[s], 2);
  }
  if (qk == 0) {
    #pragma unroll
    for (int s = 0; s < 4; ++s) {
      int r = wm * 32 + (s >> 1) * 16 + (s & 1) * 8 + qrow;
      rowLp[wn * BM + r] = rsum[s];
    }
  }

  if (wn == 1) {
    #pragma unroll
    for (int mt = 0; mt < 2; ++mt) {
      const int r = wm * 32 + mt * 16 + qrow;
      #pragma unroll
      for (int ntd = 0; ntd < 4; ++ntd) {
        const int cb = ntd * 8 + 2 * qk;
        *reinterpret_cast<float2*>(&Obuf[r * OPITCH + cb]) =
            make_float2(O[mt][ntd][0], O[mt][ntd][1]);
        *reinterpret_cast<float2*>(&Obuf[(r + 8) * OPITCH + cb]) =
            make_float2(O[mt][ntd][2], O[mt][ntd][3]);
      }
    }
  }
  __syncthreads();

  if (tid < BM) {
    const int row = tid;
    const int t = t0 + row;
    const float* qt = base + (size_t)t * DH;
    float d0 = 0.f, d1 = 0.f, d2 = 0.f;
    #pragma unroll
    for (int kk = 0; kk < DH; ++kk) { float q = qt[kk]; d1 = fmaf(q, q, d1); }
    if (t > 0) {
      const float* km = base + (size_t)(t - 1) * DH;
      #pragma unroll
      for (int kk = 0; kk < DH; ++kk) d0 = fmaf(qt[kk], km[kk], d0);
    }
    if (t < MLEN - 1) {
      const float* kp = base + (size_t)(t + 1) * DH;
      #pragma unroll
      for (int kk = 0; kk < DH; ++kk) d2 = fmaf(qt[kk], kp[kk], d2);
    }
    float e0 = (t > 0)        ? d0 * scale : 0.0f;
    float e1 = d1 * scale;
    float e2 = (t < MLEN - 1) ? d2 * scale : 0.0f;
    float p0 = __expf(e0), p1 = __expf(e1), p2 = __expf(e2);
    float L = rowLp[row] + rowLp[BM + row] + p0 + p1 + p2;
    pe0[row] = (t > 0)        ? p0 : 0.0f;
    pe1[row] = p1;
    pe2[row] = (t < MLEN - 1) ? p2 : 0.0f;
    linv[row] = 1.0f / L;
  }
  __syncthreads();

  if (wn == 0) {
    #pragma unroll
    for (int mt = 0; mt < 2; ++mt) {
      #pragma unroll
      for (int half = 0; half < 2; ++half) {
        const int r = wm * 32 + mt * 16 + half * 8 + qrow;
        const int t = t0 + r;
        const int n = 2 * t + rbit;
        if (n >= SEQ) continue;
        const float inv = linv[r];
        const float w0 = pe0[r], w1 = pe1[r], w2 = pe2[r];
        #pragma unroll
        for (int ntd = 0; ntd < 4; ++ntd) {
          const int cb = ntd * 8 + 2 * qk;
          float2 oo = *reinterpret_cast<const float2*>(&Obuf[r * OPITCH + cb]);
          float ax = O[mt][ntd][half * 2 + 0] + oo.x;
          float ay = O[mt][ntd][half * 2 + 1] + oo.y;
          float2 vc = *reinterpret_cast<const float2*>(&base[(size_t)t * DH + cb]);
          ax = fmaf(w1, vc.x, ax);
          ay = fmaf(w1, vc.y, ay);
          if (t > 0) {
            float2 vm = *reinterpret_cast<const float2*>(&base[(size_t)(t - 1) * DH + cb]);
            ax = fmaf(w0, vm.x, ax);
            ay = fmaf(w0, vm.y, ay);
          }
          if (t < MLEN - 1) {
            float2 vp = *reinterpret_cast<const float2*>(&base[(size_t)(t + 1) * DH + cb]);
            ax = fmaf(w2, vp.x, ax);
            ay = fmaf(w2, vp.y, ay);
          }
          *reinterpret_cast<float2*>(
              &out[((size_t)b * SEQ + n) * DMODEL + h * DH + cb]) =
              make_float2(ax * inv, ay * inv);
        }
      }
    }
  }
}

// ---------------------------------------------------------------------------
extern "C" void kernel_launch(void* const* d_in, const int* in_sizes, int n_in,
                              void* d_out, int out_size) {
  const float* x    = (const float*)d_in[0];
  const float* W    = (const float*)d_in[1];
  const float* bias = (const float*)d_in[2];
  float* out = (float*)d_out;

  w_transpose<<<256, 256>>>(W);
  qkv_gemm<<<dim3(BATCH * NPAD / 128, DMODEL / 64), 256>>>(x, bias);
  attn<<<NPROB * (MLEN / BM), 128>>>(out);
}

// round 7
// speedup vs baseline: 4.9903x; 1.0240x over previous
#include <cuda_runtime.h>
#include <cstdint>

#define HEADS   8
#define DH      32
#define MLEN    1024
#define NPROB   64          // B * HEADS * RATE
#define BATCH   4
#define SEQ     2046
#define NPAD    2048
#define DMODEL  256

#define BM      64
#define BN      64
#define OPITCH  34          // Obuf pitch (even, conflict-free across qrow)

__device__ float g_qkv[NPROB * MLEN * DH];
__device__ uint32_t g_WT[DMODEL * DMODEL];   // W^T in tf32, [c][d]

// ---------------------------------------------------------------------------
// tf32 helpers
// ---------------------------------------------------------------------------
__device__ __forceinline__ uint32_t f2tf32(float f) {
  uint32_t u;
  asm("cvt.rna.tf32.f32 %0, %1;" : "=r"(u) : "f"(f));
  return u;
}

__device__ __forceinline__ void mma_tf32(float c[4],
    uint32_t a0, uint32_t a1, uint32_t a2, uint32_t a3,
    uint32_t b0, uint32_t b1) {
  asm volatile(
    "mma.sync.aligned.m16n8k8.row.col.f32.tf32.tf32.f32 "
    "{%0,%1,%2,%3},{%4,%5,%6,%7},{%8,%9},{%0,%1,%2,%3};"
    : "+f"(c[0]), "+f"(c[1]), "+f"(c[2]), "+f"(c[3])
    : "r"(a0), "r"(a1), "r"(a2), "r"(a3), "r"(b0), "r"(b1));
}

// ---------------------------------------------------------------------------
// Kernel 0: W^T -> tf32 (one-time, tiny). float4 reads, 4 scattered writes.
// ---------------------------------------------------------------------------
__global__ __launch_bounds__(256) void w_transpose(const float* __restrict__ W) {
  int q = blockIdx.x * 256 + threadIdx.x;      // float4 index, 16384 total
  int d = q >> 6, c = (q & 63) << 2;
  float4 v = *reinterpret_cast<const float4*>(W + ((size_t)d << 8) + c);
  g_WT[(c + 0) * DMODEL + d] = f2tf32(v.x);
  g_WT[(c + 1) * DMODEL + d] = f2tf32(v.y);
  g_WT[(c + 2) * DMODEL + d] = f2tf32(v.z);
  g_WT[(c + 3) * DMODEL + d] = f2tf32(v.w);
}

// ---------------------------------------------------------------------------
// Kernel 1: qkv = pad(x) @ W + b on tensor cores (tf32), scatter into
// per-problem [1024,32] layout (unchanged from R6).
// ---------------------------------------------------------------------------
__global__ __launch_bounds__(256) void qkv_gemm(
    const float* __restrict__ x, const float* __restrict__ bias) {
  __shared__ __align__(16) uint32_t Xs[128 * 32];
  __shared__ __align__(16) uint32_t Ws[64 * 32];
  const int m0 = blockIdx.x * 128;
  const int n0 = blockIdx.y * 64;
  const int tid = threadIdx.x;
  const int warp = tid >> 5, lane = tid & 31;
  const int wm = warp >> 1, wn = warp & 1;
  const int qrow = lane >> 2, qk = lane & 3;
  const uint32_t swzA = (uint32_t)(qrow << 2);

  float C[2][4][4];
  #pragma unroll
  for (int i = 0; i < 2; ++i)
    #pragma unroll
    for (int j = 0; j < 4; ++j)
      #pragma unroll
      for (int k = 0; k < 4; ++k) C[i][j][k] = 0.0f;

  for (int kc0 = 0; kc0 < DMODEL; kc0 += 32) {
    #pragma unroll
    for (int e = 0; e < 4; ++e) {
      int f = tid + 256 * e;
      int r = f >> 3, c4 = (f & 7) << 2;
      int m = m0 + r;
      int b = m >> 11, n = m & 2047;
      uint4 u = make_uint4(0u, 0u, 0u, 0u);
      if (n < SEQ) {
        float4 v = *reinterpret_cast<const float4*>(
            x + ((size_t)b * SEQ + n) * DMODEL + kc0 + c4);
        u.x = f2tf32(v.x); u.y = f2tf32(v.y);
        u.z = f2tf32(v.z); u.w = f2tf32(v.w);
      }
      *reinterpret_cast<uint4*>(&Xs[r * 32 + (c4 ^ ((r & 7) << 2))]) = u;
    }
    #pragma unroll
    for (int e = 0; e < 2; ++e) {
      int f = tid + 256 * e;
      int r = f >> 3, c4 = (f & 7) << 2;
      uint4 u = *reinterpret_cast<const uint4*>(
          g_WT + (size_t)(n0 + r) * DMODEL + kc0 + c4);
      *reinterpret_cast<uint4*>(&Ws[r * 32 + (c4 ^ ((r & 7) << 2))]) = u;
    }
    __syncthreads();

    #pragma unroll
    for (int ks = 0; ks < 4; ++ks) {
      const int k0 = ks * 8 + qk;
      uint32_t a[2][4];
      #pragma unroll
      for (int mt = 0; mt < 2; ++mt) {
        const int rb = wm * 32 + mt * 16 + qrow;
        a[mt][0] = Xs[rb * 32 + (k0 ^ swzA)];
        a[mt][1] = Xs[(rb + 8) * 32 + (k0 ^ swzA)];
        a[mt][2] = Xs[rb * 32 + ((k0 + 4) ^ swzA)];
        a[mt][3] = Xs[(rb + 8) * 32 + ((k0 + 4) ^ swzA)];
      }
      uint32_t bf[4][2];
      #pragma unroll
      for (int nt = 0; nt < 4; ++nt) {
        const int nc = wn * 32 + nt * 8 + qrow;
        bf[nt][0] = Ws[nc * 32 + (k0 ^ swzA)];
        bf[nt][1] = Ws[nc * 32 + ((k0 + 4) ^ swzA)];
      }
      #pragma unroll
      for (int mt = 0; mt < 2; ++mt)
        #pragma unroll
        for (int nt = 0; nt < 4; ++nt)
          mma_tf32(C[mt][nt], a[mt][0], a[mt][1], a[mt][2], a[mt][3],
                   bf[nt][0], bf[nt][1]);
    }
    __syncthreads();
  }

  #pragma unroll
  for (int nt = 0; nt < 4; ++nt) {
    const int col = n0 + wn * 32 + nt * 8 + 2 * qk;
    const float bx = bias[col], by = bias[col + 1];
    const int h = col >> 5, dd = col & 31;
    #pragma unroll
    for (int mt = 0; mt < 2; ++mt) {
      #pragma unroll
      for (int half = 0; half < 2; ++half) {
        const int r = wm * 32 + mt * 16 + half * 8 + qrow;
        const int m = m0 + r;
        const int b = m >> 11, n = m & 2047;
        const int i = n >> 1, rbit = n & 1;
        float2 val = make_float2(C[mt][nt][half * 2 + 0] + bx,
                                 C[mt][nt][half * 2 + 1] + by);
        *reinterpret_cast<float2*>(
            &g_qkv[((((size_t)b * HEADS + h) * 2 + rbit) * MLEN + i) * DH + dd]) =
            val;
      }
    }
  }
}

// ---------------------------------------------------------------------------
// Kernel 2: tensor-core flash attention. Changes vs R6:
//  - exp2 folding: K pre-scaled by scale*log2(e), exp2f everywhere
//  - loop-top next-tile fill (no long-lived prefetch registers)
//  - __launch_bounds__(128, 4) -> 4 blocks/SM
// ---------------------------------------------------------------------------
__global__ __launch_bounds__(128, 4) void attn(float* __restrict__ out) {
  const int blk  = blockIdx.x;
  const int prob = blk >> 4;
  const int tile = blk & 15;
  const int t0   = tile * BM;
  const int rbit = prob & 1;
  const int h    = (prob >> 1) & 7;
  const int b    = prob >> 4;
  const float* __restrict__ base = g_qkv + (size_t)prob * (MLEN * DH);
  const int tid  = threadIdx.x;
  const int warp = tid >> 5, lane = tid & 31;
  const int wm = warp >> 1, wn = warp & 1;
  const int qrow = lane >> 2, qk = lane & 3;
  const uint32_t swzA = (uint32_t)(qrow << 2);
  const float scale2 = 0.17677669529663687f * 1.4426950408889634f; // /sqrt(32)*log2e

  __shared__ __align__(16) uint32_t Ks[BM * 32];
  __shared__ __align__(16) uint32_t Qs[2][BN * 32];
  __shared__ float Obuf[BM * OPITCH];
  __shared__ float rowLp[2 * BM];
  __shared__ float pe0[BM], pe1[BM], pe2[BM], linv[BM];

  #pragma unroll
  for (int e = 0; e < 4; ++e) {
    int f = tid + 128 * e;
    int r = f >> 3, c = (f & 7) << 2;
    float4 v = *reinterpret_cast<const float4*>(base + (size_t)(t0 + r) * DH + c);
    uint4 u;
    u.x = f2tf32(v.x * scale2); u.y = f2tf32(v.y * scale2);
    u.z = f2tf32(v.z * scale2); u.w = f2tf32(v.w * scale2);
    *reinterpret_cast<uint4*>(&Ks[r * 32 + (c ^ ((r & 7) << 2))]) = u;
  }
  #pragma unroll
  for (int e = 0; e < 4; ++e) {
    int f = tid + 128 * e;
    int r = f >> 3, c = (f & 7) << 2;
    float4 v = *reinterpret_cast<const float4*>(base + (size_t)r * DH + c);
    uint4 u;
    u.x = f2tf32(v.x); u.y = f2tf32(v.y); u.z = f2tf32(v.z); u.w = f2tf32(v.w);
    *reinterpret_cast<uint4*>(&Qs[0][r * 32 + (c ^ ((r & 7) << 2))]) = u;
  }
  __syncthreads();

  uint32_t A[2][4][4];
  #pragma unroll
  for (int mt = 0; mt < 2; ++mt) {
    const int rb = wm * 32 + mt * 16 + qrow;
    #pragma unroll
    for (int kc = 0; kc < 4; ++kc) {
      const int k0 = kc * 8 + qk;
      A[mt][kc][0] = Ks[rb * 32 + (k0 ^ swzA)];
      A[mt][kc][1] = Ks[(rb + 8) * 32 + (k0 ^ swzA)];
      A[mt][kc][2] = Ks[rb * 32 + ((k0 + 4) ^ swzA)];
      A[mt][kc][3] = Ks[(rb + 8) * 32 + ((k0 + 4) ^ swzA)];
    }
  }

  float O[2][4][4];
  #pragma unroll
  for (int i = 0; i < 2; ++i)
    #pragma unroll
    for (int j = 0; j < 4; ++j)
      #pragma unroll
      for (int k = 0; k < 4; ++k) O[i][j][k] = 0.0f;
  float rsum[4] = {0.f, 0.f, 0.f, 0.f};

  for (int it = 0; it < MLEN / BN; ++it) {
    const uint32_t* __restrict__ Qc = Qs[it & 1];

    // ---- fill NEXT tile at loop top (write buf[(it+1)&1], read buf[it&1];
    //      the end-of-previous-iteration barrier protects both) ----
    if (it < MLEN / BN - 1) {
      const float* nsrc = base + (size_t)(it + 1) * BN * DH;
      uint32_t* Qn = Qs[(it + 1) & 1];
      #pragma unroll
      for (int e = 0; e < 4; ++e) {
        int f = tid + 128 * e;
        int r = f >> 3, c = (f & 7) << 2;
        float4 v = *reinterpret_cast<const float4*>(nsrc + r * 32 + c);
        uint4 u;
        u.x = f2tf32(v.x); u.y = f2tf32(v.y);
        u.z = f2tf32(v.z); u.w = f2tf32(v.w);
        *reinterpret_cast<uint4*>(&Qn[r * 32 + (c ^ ((r & 7) << 2))]) = u;
      }
    }

    #pragma unroll
    for (int g = 0; g < 4; ++g) {
      float acc[2][4] = {{0.f,0.f,0.f,0.f},{0.f,0.f,0.f,0.f}};
      const int nc = wn * 32 + g * 8 + qrow;
      #pragma unroll
      for (int kc = 0; kc < 4; ++kc) {
        const int k0 = kc * 8 + qk;
        uint32_t b0 = Qc[nc * 32 + (k0 ^ swzA)];
        uint32_t b1 = Qc[nc * 32 + ((k0 + 4) ^ swzA)];
        mma_tf32(acc[0], A[0][kc][0], A[0][kc][1], A[0][kc][2], A[0][kc][3], b0, b1);
        mma_tf32(acc[1], A[1][kc][0], A[1][kc][1], A[1][kc][2], A[1][kc][3], b0, b1);
      }

      uint32_t aP[2][4];
      #pragma unroll
      for (int mt = 0; mt < 2; ++mt) {
        float p0 = exp2f(acc[mt][0]);
        float p1 = exp2f(acc[mt][1]);
        float p2 = exp2f(acc[mt][2]);
        float p3 = exp2f(acc[mt][3]);
        rsum[mt * 2 + 0] += p0 + p1;
        rsum[mt * 2 + 1] += p2 + p3;
        aP[mt][0] = f2tf32(p0);
        aP[mt][1] = f2tf32(p2);
        aP[mt][2] = f2tf32(p1);
        aP[mt][3] = f2tf32(p3);
      }

      const int jr0 = wn * 32 + g * 8 + 2 * qk;
      const int jr1 = jr0 + 1;
      const uint32_t swz0 = (uint32_t)((jr0 & 7) << 2);
      const uint32_t swz1 = (uint32_t)((jr1 & 7) << 2);
      #pragma unroll
      for (int ntd = 0; ntd < 4; ++ntd) {
        const int d = ntd * 8 + qrow;
        uint32_t vb0 = Qc[jr0 * 32 + (d ^ swz0)];
        uint32_t vb1 = Qc[jr1 * 32 + (d ^ swz1)];
        mma_tf32(O[0][ntd], aP[0][0], aP[0][1], aP[0][2], aP[0][3], vb0, vb1);
        mma_tf32(O[1][ntd], aP[1][0], aP[1][1], aP[1][2], aP[1][3], vb0, vb1);
      }
    }
    __syncthreads();
  }

  #pragma unroll
  for (int s = 0; s < 4; ++s) {
    rsum[s] += __shfl_xor_sync(0xffffffffu, rsum[s], 1);
    rsum[s] += __shfl_xor_sync(0xffffffffu, rsum[s], 2);
  }
  if (qk == 0) {
    #pragma unroll
    for (int s = 0; s < 4; ++s) {
      int r = wm * 32 + (s >> 1) * 16 + (s & 1) * 8 + qrow;
      rowLp[wn * BM + r] = rsum[s];
    }
  }

  if (wn == 1) {
    #pragma unroll
    for (int mt = 0; mt < 2; ++mt) {
      const int r = wm * 32 + mt * 16 + qrow;
      #pragma unroll
      for (int ntd = 0; ntd < 4; ++ntd) {
        const int cb = ntd * 8 + 2 * qk;
        *reinterpret_cast<float2*>(&Obuf[r * OPITCH + cb]) =
            make_float2(O[mt][ntd][0], O[mt][ntd][1]);
        *reinterpret_cast<float2*>(&Obuf[(r + 8) * OPITCH + cb]) =
            make_float2(O[mt][ntd][2], O[mt][ntd][3]);
      }
    }
  }
  __syncthreads();

  if (tid < BM) {
    const int row = tid;
    const int t = t0 + row;
    const float* qt = base + (size_t)t * DH;
    float d0 = 0.f, d1 = 0.f, d2 = 0.f;
    #pragma unroll
    for (int kk = 0; kk < DH; ++kk) { float q = qt[kk]; d1 = fmaf(q, q, d1); }
    if (t > 0) {
      const float* km = base + (size_t)(t - 1) * DH;
      #pragma unroll
      for (int kk = 0; kk < DH; ++kk) d0 = fmaf(qt[kk], km[kk], d0);
    }
    if (t < MLEN - 1) {
      const float* kp = base + (size_t)(t + 1) * DH;
      #pragma unroll
      for (int kk = 0; kk < DH; ++kk) d2 = fmaf(qt[kk], kp[kk], d2);
    }
    float e0 = (t > 0)        ? d0 * scale2 : 0.0f;   // base-2 logits
    float e1 = d1 * scale2;
    float e2 = (t < MLEN - 1) ? d2 * scale2 : 0.0f;
    float p0 = exp2f(e0), p1 = exp2f(e1), p2 = exp2f(e2);
    float L = rowLp[row] + rowLp[BM + row] + p0 + p1 + p2;
    pe0[row] = (t > 0)        ? p0 : 0.0f;
    pe1[row] = p1;
    pe2[row] = (t < MLEN - 1) ? p2 : 0.0f;
    linv[row] = 1.0f / L;
  }
  __syncthreads();

  if (wn == 0) {
    #pragma unroll
    for (int mt = 0; mt < 2; ++mt) {
      #pragma unroll
      for (int half = 0; half < 2; ++half) {
        const int r = wm * 32 + mt * 16 + half * 8 + qrow;
        const int t = t0 + r;
        const int n = 2 * t + rbit;
        if (n >= SEQ) continue;
        const float inv = linv[r];
        const float w0 = pe0[r], w1 = pe1[r], w2 = pe2[r];
        #pragma unroll
        for (int ntd = 0; ntd < 4; ++ntd) {
          const int cb = ntd * 8 + 2 * qk;
          float2 oo = *reinterpret_cast<const float2*>(&Obuf[r * OPITCH + cb]);
          float ax = O[mt][ntd][half * 2 + 0] + oo.x;
          float ay = O[mt][ntd][half * 2 + 1] + oo.y;
          float2 vc = *reinterpret_cast<const float2*>(&base[(size_t)t * DH + cb]);
          ax = fmaf(w1, vc.x, ax);
          ay = fmaf(w1, vc.y, ay);
          if (t > 0) {
            float2 vm = *reinterpret_cast<const float2*>(&base[(size_t)(t - 1) * DH + cb]);
            ax = fmaf(w0, vm.x, ax);
            ay = fmaf(w0, vm.y, ay);
          }
          if (t < MLEN - 1) {
            float2 vp = *reinterpret_cast<const float2*>(&base[(size_t)(t + 1) * DH + cb]);
            ax = fmaf(w2, vp.x, ax);
            ay = fmaf(w2, vp.y, ay);
          }
          *reinterpret_cast<float2*>(
              &out[((size_t)b * SEQ + n) * DMODEL + h * DH + cb]) =
              make_float2(ax * inv, ay * inv);
        }
      }
    }
  }
}

// ---------------------------------------------------------------------------
extern "C" void kernel_launch(void* const* d_in, const int* in_sizes, int n_in,
                              void* d_out, int out_size) {
  const float* x    = (const float*)d_in[0];
  const float* W    = (const float*)d_in[1];
  const float* bias = (const float*)d_in[2];
  float* out = (float*)d_out;

  w_transpose<<<64, 256>>>(W);
  qkv_gemm<<<dim3(BATCH * NPAD / 128, DMODEL / 64), 256>>>(x, bias);
  attn<<<NPROB * (MLEN / BM), 128>>>(out);
}

// round 8
// speedup vs baseline: 5.2989x; 1.0618x over previous
#include <cuda_runtime.h>
#include <cstdint>

#define HEADS   8
#define DH      32
#define MLEN    1024
#define NPROB   64          // B * HEADS * RATE
#define BATCH   4
#define SEQ     2046
#define NPAD    2048
#define DMODEL  256

#define BM      64
#define BN      64
#define OPITCH  34          // Obuf pitch (even, conflict-free across qrow)

__device__ float g_qkv[NPROB * MLEN * DH];

// ---------------------------------------------------------------------------
// helpers
// ---------------------------------------------------------------------------
__device__ __forceinline__ uint32_t f2tf32(float f) {
  uint32_t u;
  asm("cvt.rna.tf32.f32 %0, %1;" : "=r"(u) : "f"(f));
  return u;
}

__device__ __forceinline__ void mma_tf32(float c[4],
    uint32_t a0, uint32_t a1, uint32_t a2, uint32_t a3,
    uint32_t b0, uint32_t b1) {
  asm volatile(
    "mma.sync.aligned.m16n8k8.row.col.f32.tf32.tf32.f32 "
    "{%0,%1,%2,%3},{%4,%5,%6,%7},{%8,%9},{%0,%1,%2,%3};"
    : "+f"(c[0]), "+f"(c[1]), "+f"(c[2]), "+f"(c[3])
    : "r"(a0), "r"(a1), "r"(a2), "r"(a3), "r"(b0), "r"(b1));
}

__device__ __forceinline__ void cp16(uint32_t dst_smem, const void* src) {
  asm volatile("cp.async.cg.shared.global [%0], [%1], 16;"
               :: "r"(dst_smem), "l"(src));
}
__device__ __forceinline__ void cp_commit() {
  asm volatile("cp.async.commit_group;");
}
__device__ __forceinline__ void cp_wait0() {
  asm volatile("cp.async.wait_group 0;");
}

// ---------------------------------------------------------------------------
// Kernel 1: qkv = pad(x) @ W + b on tensor cores (tf32); W transposed into
// smem on the fly (no separate transpose kernel). Scatter into per-problem
// [1024,32] layout.
// ---------------------------------------------------------------------------
__global__ __launch_bounds__(256) void qkv_gemm(
    const float* __restrict__ x, const float* __restrict__ W,
    const float* __restrict__ bias) {
  __shared__ __align__(16) uint32_t Xs[128 * 32];
  __shared__ __align__(16) uint32_t Ws[64 * 32];
  const int m0 = blockIdx.x * 128;
  const int n0 = blockIdx.y * 64;
  const int tid = threadIdx.x;
  const int warp = tid >> 5, lane = tid & 31;
  const int wm = warp >> 1, wn = warp & 1;
  const int qrow = lane >> 2, qk = lane & 3;
  const uint32_t swzA = (uint32_t)(qrow << 2);

  float C[2][4][4];
  #pragma unroll
  for (int i = 0; i < 2; ++i)
    #pragma unroll
    for (int j = 0; j < 4; ++j)
      #pragma unroll
      for (int k = 0; k < 4; ++k) C[i][j][k] = 0.0f;

  for (int kc0 = 0; kc0 < DMODEL; kc0 += 32) {
    // ---- fill Xs[128][32] (tf32, swizzled); padded rows -> 0 ----
    #pragma unroll
    for (int e = 0; e < 4; ++e) {
      int f = tid + 256 * e;
      int r = f >> 3, c4 = (f & 7) << 2;
      int m = m0 + r;
      int b = m >> 11, n = m & 2047;
      uint4 u = make_uint4(0u, 0u, 0u, 0u);
      if (n < SEQ) {
        float4 v = *reinterpret_cast<const float4*>(
            x + ((size_t)b * SEQ + n) * DMODEL + kc0 + c4);
        u.x = f2tf32(v.x); u.y = f2tf32(v.y);
        u.z = f2tf32(v.z); u.w = f2tf32(v.w);
      }
      *reinterpret_cast<uint4*>(&Xs[r * 32 + (c4 ^ ((r & 7) << 2))]) = u;
    }
    // ---- fill Ws[64][32] = W^T tile: read W[kc0+c][n0+r..r+3] (coalesced),
    //      write transposed+swizzled+cvt ----
    #pragma unroll
    for (int e = 0; e < 2; ++e) {
      int u = tid + 256 * e;          // 512 float4-groups
      int c = u >> 4, r4 = (u & 15) << 2;
      float4 v = *reinterpret_cast<const float4*>(
          W + (size_t)(kc0 + c) * DMODEL + n0 + r4);
      Ws[(r4 + 0) * 32 + (c ^ (((r4 + 0) & 7) << 2))] = f2tf32(v.x);
      Ws[(r4 + 1) * 32 + (c ^ (((r4 + 1) & 7) << 2))] = f2tf32(v.y);
      Ws[(r4 + 2) * 32 + (c ^ (((r4 + 2) & 7) << 2))] = f2tf32(v.z);
      Ws[(r4 + 3) * 32 + (c ^ (((r4 + 3) & 7) << 2))] = f2tf32(v.w);
    }
    __syncthreads();

    #pragma unroll
    for (int ks = 0; ks < 4; ++ks) {
      const int k0 = ks * 8 + qk;
      uint32_t a[2][4];
      #pragma unroll
      for (int mt = 0; mt < 2; ++mt) {
        const int rb = wm * 32 + mt * 16 + qrow;
        a[mt][0] = Xs[rb * 32 + (k0 ^ swzA)];
        a[mt][1] = Xs[(rb + 8) * 32 + (k0 ^ swzA)];
        a[mt][2] = Xs[rb * 32 + ((k0 + 4) ^ swzA)];
        a[mt][3] = Xs[(rb + 8) * 32 + ((k0 + 4) ^ swzA)];
      }
      uint32_t bf[4][2];
      #pragma unroll
      for (int nt = 0; nt < 4; ++nt) {
        const int nc = wn * 32 + nt * 8 + qrow;
        bf[nt][0] = Ws[nc * 32 + (k0 ^ swzA)];
        bf[nt][1] = Ws[nc * 32 + ((k0 + 4) ^ swzA)];
      }
      #pragma unroll
      for (int mt = 0; mt < 2; ++mt)
        #pragma unroll
        for (int nt = 0; nt < 4; ++nt)
          mma_tf32(C[mt][nt], a[mt][0], a[mt][1], a[mt][2], a[mt][3],
                   bf[nt][0], bf[nt][1]);
    }
    __syncthreads();
  }

  #pragma unroll
  for (int nt = 0; nt < 4; ++nt) {
    const int col = n0 + wn * 32 + nt * 8 + 2 * qk;
    const float bx = bias[col], by = bias[col + 1];
    const int h = col >> 5, dd = col & 31;
    #pragma unroll
    for (int mt = 0; mt < 2; ++mt) {
      #pragma unroll
      for (int half = 0; half < 2; ++half) {
        const int r = wm * 32 + mt * 16 + half * 8 + qrow;
        const int m = m0 + r;
        const int b = m >> 11, n = m & 2047;
        const int i = n >> 1, rbit = n & 1;
        float2 val = make_float2(C[mt][nt][half * 2 + 0] + bx,
                                 C[mt][nt][half * 2 + 1] + by);
        *reinterpret_cast<float2*>(
            &g_qkv[((((size_t)b * HEADS + h) * 2 + rbit) * MLEN + i) * DH + dd]) =
            val;
      }
    }
  }
}

// ---------------------------------------------------------------------------
// Kernel 2: tensor-core flash attention. vs R7:
//  - cp.async tile fill (issue at top, wait at bottom): no STS stall, no
//    prefetch registers. Q/V stored raw fp32 (tf32 MMA truncates low bits).
//  - Obuf aliased onto Ks (dead after A-frag hoist): smem 34.8 -> 26.6 KB,
//    guaranteeing 4 blocks/SM with __launch_bounds__(128, 4).
// ---------------------------------------------------------------------------
__global__ __launch_bounds__(128, 4) void attn(float* __restrict__ out) {
  const int blk  = blockIdx.x;
  const int prob = blk >> 4;
  const int tile = blk & 15;
  const int t0   = tile * BM;
  const int rbit = prob & 1;
  const int h    = (prob >> 1) & 7;
  const int b    = prob >> 4;
  const float* __restrict__ base = g_qkv + (size_t)prob * (MLEN * DH);
  const int tid  = threadIdx.x;
  const int warp = tid >> 5, lane = tid & 31;
  const int wm = warp >> 1, wn = warp & 1;
  const int qrow = lane >> 2, qk = lane & 3;
  const uint32_t swzA = (uint32_t)(qrow << 2);
  const float scale2 = 0.17677669529663687f * 1.4426950408889634f; // /sqrt(32)*log2e

  __shared__ __align__(16) char KsObuf[BM * OPITCH * 4];  // Ks then Obuf
  __shared__ __align__(16) uint32_t Qs[2][BN * 32];
  __shared__ float rowLp[2 * BM];
  __shared__ float pe0[BM], pe1[BM], pe2[BM], linv[BM];
  uint32_t* Ks  = reinterpret_cast<uint32_t*>(KsObuf);
  float*   Obuf = reinterpret_cast<float*>(KsObuf);

  const uint32_t qsBase = (uint32_t)__cvta_generic_to_shared(&Qs[0][0]);

  // ---- async-fill Qs[0] (raw fp32; tf32 MMA truncates) ----
  #pragma unroll
  for (int e = 0; e < 4; ++e) {
    int f = tid + 128 * e;
    int r = f >> 3, c = (f & 7) << 2;
    cp16(qsBase + (uint32_t)(r * 32 + (c ^ ((r & 7) << 2))) * 4,
         base + (size_t)r * DH + c);
  }
  cp_commit();

  // ---- fill Ks (scaled by scale*log2e, rounded tf32, swizzled) ----
  #pragma unroll
  for (int e = 0; e < 4; ++e) {
    int f = tid + 128 * e;
    int r = f >> 3, c = (f & 7) << 2;
    float4 v = *reinterpret_cast<const float4*>(base + (size_t)(t0 + r) * DH + c);
    uint4 u;
    u.x = f2tf32(v.x * scale2); u.y = f2tf32(v.y * scale2);
    u.z = f2tf32(v.z * scale2); u.w = f2tf32(v.w * scale2);
    *reinterpret_cast<uint4*>(&Ks[r * 32 + (c ^ ((r & 7) << 2))]) = u;
  }
  cp_wait0();
  __syncthreads();

  // ---- hoist K A-fragments (Ks dead afterwards -> Obuf reuses its smem) ----
  uint32_t A[2][4][4];
  #pragma unroll
  for (int mt = 0; mt < 2; ++mt) {
    const int rb = wm * 32 + mt * 16 + qrow;
    #pragma unroll
    for (int kc = 0; kc < 4; ++kc) {
      const int k0 = kc * 8 + qk;
      A[mt][kc][0] = Ks[rb * 32 + (k0 ^ swzA)];
      A[mt][kc][1] = Ks[(rb + 8) * 32 + (k0 ^ swzA)];
      A[mt][kc][2] = Ks[rb * 32 + ((k0 + 4) ^ swzA)];
      A[mt][kc][3] = Ks[(rb + 8) * 32 + ((k0 + 4) ^ swzA)];
    }
  }
  __syncthreads();   // all warps done reading Ks before Obuf writes (later)

  float O[2][4][4];
  #pragma unroll
  for (int i = 0; i < 2; ++i)
    #pragma unroll
    for (int j = 0; j < 4; ++j)
      #pragma unroll
      for (int k = 0; k < 4; ++k) O[i][j][k] = 0.0f;
  float rsum[4] = {0.f, 0.f, 0.f, 0.f};

  for (int it = 0; it < MLEN / BN; ++it) {
    const uint32_t* __restrict__ Qc = Qs[it & 1];

    // ---- async-fill NEXT tile (no stall: data lands during compute) ----
    if (it < MLEN / BN - 1) {
      const float* nsrc = base + (size_t)(it + 1) * BN * DH;
      const uint32_t dstBase = qsBase + (uint32_t)(((it + 1) & 1) * BN * 32) * 4;
      #pragma unroll
      for (int e = 0; e < 4; ++e) {
        int f = tid + 128 * e;
        int r = f >> 3, c = (f & 7) << 2;
        cp16(dstBase + (uint32_t)(r * 32 + (c ^ ((r & 7) << 2))) * 4,
             nsrc + r * 32 + c);
      }
    }
    cp_commit();

    #pragma unroll
    for (int g = 0; g < 4; ++g) {
      float acc[2][4] = {{0.f,0.f,0.f,0.f},{0.f,0.f,0.f,0.f}};
      const int nc = wn * 32 + g * 8 + qrow;
      #pragma unroll
      for (int kc = 0; kc < 4; ++kc) {
        const int k0 = kc * 8 + qk;
        uint32_t b0 = Qc[nc * 32 + (k0 ^ swzA)];
        uint32_t b1 = Qc[nc * 32 + ((k0 + 4) ^ swzA)];
        mma_tf32(acc[0], A[0][kc][0], A[0][kc][1], A[0][kc][2], A[0][kc][3], b0, b1);
        mma_tf32(acc[1], A[1][kc][0], A[1][kc][1], A[1][kc][2], A[1][kc][3], b0, b1);
      }

      uint32_t aP[2][4];
      #pragma unroll
      for (int mt = 0; mt < 2; ++mt) {
        float p0 = exp2f(acc[mt][0]);
        float p1 = exp2f(acc[mt][1]);
        float p2 = exp2f(acc[mt][2]);
        float p3 = exp2f(acc[mt][3]);
        rsum[mt * 2 + 0] += p0 + p1;
        rsum[mt * 2 + 1] += p2 + p3;
        aP[mt][0] = f2tf32(p0);
        aP[mt][1] = f2tf32(p2);
        aP[mt][2] = f2tf32(p1);
        aP[mt][3] = f2tf32(p3);
      }

      const int jr0 = wn * 32 + g * 8 + 2 * qk;
      const int jr1 = jr0 + 1;
      const uint32_t swz0 = (uint32_t)((jr0 & 7) << 2);
      const uint32_t swz1 = (uint32_t)((jr1 & 7) << 2);
      #pragma unroll
      for (int ntd = 0; ntd < 4; ++ntd) {
        const int d = ntd * 8 + qrow;
        uint32_t vb0 = Qc[jr0 * 32 + (d ^ swz0)];
        uint32_t vb1 = Qc[jr1 * 32 + (d ^ swz1)];
        mma_tf32(O[0][ntd], aP[0][0], aP[0][1], aP[0][2], aP[0][3], vb0, vb1);
        mma_tf32(O[1][ntd], aP[1][0], aP[1][1], aP[1][2], aP[1][3], vb0, vb1);
      }
    }
    cp_wait0();
    __syncthreads();
  }

  #pragma unroll
  for (int s = 0; s < 4; ++s) {
    rsum[s] += __shfl_xor_sync(0xffffffffu, rsum[s], 1);
    rsum[s] += __shfl_xor_sync(0xffffffffu, rsum[s], 2);
  }
  if (qk == 0) {
    #pragma unroll
    for (int s = 0; s < 4; ++s) {
      int r = wm * 32 + (s >> 1) * 16 + (s & 1) * 8 + qrow;
      rowLp[wn * BM + r] = rsum[s];
    }
  }

  if (wn == 1) {
    #pragma unroll
    for (int mt = 0; mt < 2; ++mt) {
      const int r = wm * 32 + mt * 16 + qrow;
      #pragma unroll
      for (int ntd = 0; ntd < 4; ++ntd) {
        const int cb = ntd * 8 + 2 * qk;
        *reinterpret_cast<float2*>(&Obuf[r * OPITCH + cb]) =
            make_float2(O[mt][ntd][0], O[mt][ntd][1]);
        *reinterpret_cast<float2*>(&Obuf[(r + 8) * OPITCH + cb]) =
            make_float2(O[mt][ntd][2], O[mt][ntd][3]);
      }
    }
  }
  __syncthreads();

  if (tid < BM) {
    const int row = tid;
    const int t = t0 + row;
    const float* qt = base + (size_t)t * DH;
    float d0 = 0.f, d1 = 0.f, d2 = 0.f;
    #pragma unroll
    for (int kk = 0; kk < DH; ++kk) { float q = qt[kk]; d1 = fmaf(q, q, d1); }
    if (t > 0) {
      const float* km = base + (size_t)(t - 1) * DH;
      #pragma unroll
      for (int kk = 0; kk < DH; ++kk) d0 = fmaf(qt[kk], km[kk], d0);
    }
    if (t < MLEN - 1) {
      const float* kp = base + (size_t)(t + 1) * DH;
      #pragma unroll
      for (int kk = 0; kk < DH; ++kk) d2 = fmaf(qt[kk], kp[kk], d2);
    }
    float e0 = (t > 0)        ? d0 * scale2 : 0.0f;   // base-2 logits
    float e1 = d1 * scale2;
    float e2 = (t < MLEN - 1) ? d2 * scale2 : 0.0f;
    float p0 = exp2f(e0), p1 = exp2f(e1), p2 = exp2f(e2);
    float L = rowLp[row] + rowLp[BM + row] + p0 + p1 + p2;
    pe0[row] = (t > 0)        ? p0 : 0.0f;
    pe1[row] = p1;
    pe2[row] = (t < MLEN - 1) ? p2 : 0.0f;
    linv[row] = 1.0f / L;
  }
  __syncthreads();

  if (wn == 0) {
    #pragma unroll
    for (int mt = 0; mt < 2; ++mt) {
      #pragma unroll
      for (int half = 0; half < 2; ++half) {
        const int r = wm * 32 + mt * 16 + half * 8 + qrow;
        const int t = t0 + r;
        const int n = 2 * t + rbit;
        if (n >= SEQ) continue;
        const float inv = linv[r];
        const float w0 = pe0[r], w1 = pe1[r], w2 = pe2[r];
        #pragma unroll
        for (int ntd = 0; ntd < 4; ++ntd) {
          const int cb = ntd * 8 + 2 * qk;
          float2 oo = *reinterpret_cast<const float2*>(&Obuf[r * OPITCH + cb]);
          float ax = O[mt][ntd][half * 2 + 0] + oo.x;
          float ay = O[mt][ntd][half * 2 + 1] + oo.y;
          float2 vc = *reinterpret_cast<const float2*>(&base[(size_t)t * DH + cb]);
          ax = fmaf(w1, vc.x, ax);
          ay = fmaf(w1, vc.y, ay);
          if (t > 0) {
            float2 vm = *reinterpret_cast<const float2*>(&base[(size_t)(t - 1) * DH + cb]);
            ax = fmaf(w0, vm.x, ax);
            ay = fmaf(w0, vm.y, ay);
          }
          if (t < MLEN - 1) {
            float2 vp = *reinterpret_cast<const float2*>(&base[(size_t)(t + 1) * DH + cb]);
            ax = fmaf(w2, vp.x, ax);
            ay = fmaf(w2, vp.y, ay);
          }
          *reinterpret_cast<float2*>(
              &out[((size_t)b * SEQ + n) * DMODEL + h * DH + cb]) =
              make_float2(ax * inv, ay * inv);
        }
      }
    }
  }
}

// ---------------------------------------------------------------------------
extern "C" void kernel_launch(void* const* d_in, const int* in_sizes, int n_in,
                              void* d_out, int out_size) {
  const float* x    = (const float*)d_in[0];
  const float* W    = (const float*)d_in[1];
  const float* bias = (const float*)d_in[2];
  float* out = (float*)d_out;

  qkv_gemm<<<dim3(BATCH * NPAD / 128, DMODEL / 64), 256>>>(x, W, bias);
  attn<<<NPROB * (MLEN / BM), 128>>>(out);
}